// round 7
// baseline (speedup 1.0000x reference)
#include <cuda_runtime.h>
#include <mma.h>
#include <math.h>
#include <stdint.h>

using namespace nvcuda;

#define BB 8
#define NN 20000
#define EE 40000
#define HH 128
#define TT 64
#define LL 4

__device__ __forceinline__ uint32_t f2tf(float f) {
    uint32_t u;
    asm("cvt.rna.tf32.f32 %0, %1;" : "=r"(u) : "f"(f));
    return u;
}
__device__ __forceinline__ float silu_f(float v) { return v / (1.f + __expf(-v)); }
__device__ __forceinline__ uint32_t s2u(const void* p) {
    uint32_t a;
    asm("{ .reg .u64 t; cvta.to.shared.u64 t, %1; cvt.u32.u64 %0, t; }" : "=r"(a) : "l"(p));
    return a;
}
__device__ __forceinline__ void cp16(uint32_t dst, const void* src) {
    asm volatile("cp.async.cg.shared.global [%0], [%1], 16;\n" :: "r"(dst), "l"(src));
}
#define CP_COMMIT() asm volatile("cp.async.commit_group;\n" ::: "memory")
template <int N> __device__ __forceinline__ void cp_wait() {
    asm volatile("cp.async.wait_group %0;\n" :: "n"(N) : "memory");
}

// ---------------- scratch (static device globals) --------------------------
__device__ float g_temb[BB * HH];
__device__ float g_table4[4 * HH];
__device__ float g_h[BB * NN * HH];
__device__ float g_htf[BB * NN * HH];    // tf32-rounded shadow of h
__device__ float g_agg[BB * NN * HH];    // tf32-rounded at store
__device__ float g_x[BB * NN * 3];
__device__ float g_cupd[BB * NN * 3];
__device__ float g_dist[BB * EE];
__device__ float g_cdn[BB * EE * 3];
__device__ float g_m[BB * EE * HH];
__device__ int   g_deg[NN];
__device__ int   g_off[NN + 1];
__device__ int   g_cur[NN];
__device__ int   g_csr[2 * EE];
// tf32-rounded weights
__device__ float g_wm1[4 * 257 * 128];
__device__ float g_wm2[4 * 128 * 128];
__device__ float g_wc1[4 * 128 * 128];
__device__ float g_wn1[4 * 256 * 128];
__device__ float g_wn2[4 * 128 * 128];
__device__ float g_wo1[128 * 128];

// ---------------- wmma helpers (M=64 CTA tile) ------------------------------
#define TM 64     // CTA tile rows
#define LDT 136
#define LDAs 36

using FragC = wmma::fragment<wmma::accumulator, 16, 16, 8, float>;
using FragA = wmma::fragment<wmma::matrix_a, 16, 16, 8, wmma::precision::tf32, wmma::row_major>;
using FragB = wmma::fragment<wmma::matrix_b, 16, 16, 8, wmma::precision::tf32, wmma::row_major>;

// warp wm (0..3) owns rows [wm*16, wm*16+16); warp wn (0..1) owns cols [wn*64, wn*64+64)
__device__ __forceinline__ void mma_chunk(FragC c[4], const float* Asrc, int lda,
                                          const float* Bs, int wm, int wn)
{
#pragma unroll
    for (int kk = 0; kk < 32; kk += 8) {
        FragA a;
        FragB b[4];
        wmma::load_matrix_sync(a, Asrc + (wm * 16) * lda + kk, lda);
#pragma unroll
        for (int j = 0; j < 4; j++)
            wmma::load_matrix_sync(b[j], Bs + kk * LDT + wn * 64 + j * 16, LDT);
#pragma unroll
        for (int j = 0; j < 4; j++)
            wmma::mma_sync(c[j], a, b[j], c[j]);
    }
}
__device__ __forceinline__ void zero_c(FragC c[4])
{
#pragma unroll
    for (int j = 0; j < 4; j++) wmma::fill_fragment(c[j], 0.f);
}
__device__ __forceinline__ void store_c(FragC c[4], float* T, int wm, int wn)
{
#pragma unroll
    for (int j = 0; j < 4; j++)
        wmma::store_matrix_sync(T + (wm * 16) * LDT + wn * 64 + j * 16,
                                c[j], LDT, wmma::mem_row_major);
}

// one 32-row B chunk via cp.async (pre-rounded weights)
__device__ __forceinline__ void issue_B(const float* __restrict__ W, int k0,
                                        float* Bsb, int tid)
{
    const int bkrow = tid >> 3;
    const int bnc   = (tid & 7) * 16;
    const float* src = W + (long)(k0 + bkrow) * 128 + bnc;
    uint32_t dst = s2u(Bsb + bkrow * LDT + bnc);
#pragma unroll
    for (int q = 0; q < 4; q++) cp16(dst + q * 16, src + q * 4);
}

// dyn smem: T[64*LDT] + Bs0[32*LDT] + Bs1[32*LDT] = 69632 B -> 3 CTAs/SM
#define FUSE_SMEM ((TM * LDT + 64 * LDT) * 4)

// ---------------- fused edge kernel ----------------------------------------
__global__ void __launch_bounds__(256, 3)
edge_fused_k(const float* __restrict__ Wm1tf, const float* __restrict__ bm1,
             const float* __restrict__ w256,
             const float* __restrict__ Wm2tf, const float* __restrict__ bm2,
             const float* __restrict__ Wc1tf, const float* __restrict__ bc1,
             const float* __restrict__ Wc2, const int* __restrict__ bonds)
{
    extern __shared__ float dyn[];
    float* T   = dyn;
    float* Bs0 = dyn + TM * LDT;
    float* Bs1 = Bs0 + 32 * LDT;
    float* As0 = T;
    float* As1 = T + TM * LDAs;

    __shared__ float b1s[128], b2s[128], bc1s[128], wc2s[128], wds[128];
    __shared__ const float* pA0[TM];
    __shared__ const float* pA1[TM];

    const int tid = threadIdx.x;
    const int wid = tid >> 5;
    const int wm = wid & 3, wn = wid >> 2;
    const long row0 = (long)blockIdx.x * TM;

    if (tid < 128) {
        b1s[tid] = bm1[tid]; b2s[tid] = bm2[tid];
        bc1s[tid] = bc1[tid]; wc2s[tid] = Wc2[tid]; wds[tid] = w256[tid];
    }
    if (tid < TM) {
        long gr = row0 + tid;
        int b = (int)(gr / EE), e = (int)(gr - (long)b * EE);
        int s = bonds[2 * e], d = bonds[2 * e + 1];
        pA0[tid] = g_htf + ((long)b * NN + s) * HH;
        pA1[tid] = g_htf + ((long)b * NN + d) * HH;
    }
    __syncthreads();

    const int arow = tid >> 2;          // 0..63
    const int akb  = (tid & 3) * 8;     // 8 floats = 2 cp16

    auto issue_A = [&](int ch, float* Asb) {
        int k0 = ch << 5;
        const float* src = ((k0 < 128) ? pA0[arow] : pA1[arow]) + (k0 & 127) + akb;
        uint32_t dst = s2u(Asb + arow * LDAs + akb);
        cp16(dst, src);
        cp16(dst + 16, src + 4);
    };

    FragC c[4];

    // ---- stage 1: m1 = silu(gather @ Wm1 + dist*w256 + b), K=256 ----
    zero_c(c);
    issue_A(0, As0); issue_B(Wm1tf, 0, Bs0, tid); CP_COMMIT();
    issue_A(1, As1); issue_B(Wm1tf, 32, Bs1, tid); CP_COMMIT();
    for (int ch = 0; ch < 8; ch++) {
        if (ch == 7) cp_wait<0>(); else cp_wait<1>();
        __syncthreads();
        mma_chunk(c, (ch & 1) ? As1 : As0, LDAs, (ch & 1) ? Bs1 : Bs0, wm, wn);
        __syncthreads();
        if (ch + 2 < 8) {
            issue_A(ch + 2, (ch & 1) ? As1 : As0);
            issue_B(Wm1tf, (ch + 2) * 32, (ch & 1) ? Bs1 : Bs0, tid);
            CP_COMMIT();
        }
    }
    store_c(c, T, wm, wn);
    __syncthreads();
    {
        const int row = tid >> 2, cb = (tid & 3) * 32;
        const float dv = g_dist[row0 + row];
        float* p = T + row * LDT + cb;
#pragma unroll
        for (int j = 0; j < 32; j++) {
            float v = silu_f(p[j] + b1s[cb + j] + dv * wds[cb + j]);
            ((uint32_t*)p)[j] = f2tf(v);
        }
    }
    __syncthreads();

    // ---- stage 2: m = silu(m1 @ Wm2 + b) ----
    zero_c(c);
    issue_B(Wm2tf, 0, Bs0, tid); CP_COMMIT();
    issue_B(Wm2tf, 32, Bs1, tid); CP_COMMIT();
    for (int ch = 0; ch < 4; ch++) {
        if (ch == 3) cp_wait<0>(); else cp_wait<1>();
        __syncthreads();
        mma_chunk(c, T + ch * 32, LDT, (ch & 1) ? Bs1 : Bs0, wm, wn);
        __syncthreads();
        if (ch + 2 < 4) { issue_B(Wm2tf, (ch + 2) * 32, (ch & 1) ? Bs1 : Bs0, tid); CP_COMMIT(); }
    }
    store_c(c, T, wm, wn);
    __syncthreads();
    {
        const int row = tid >> 2, cb = (tid & 3) * 32;
        const long gr = row0 + row;
        float* p = T + row * LDT + cb;
        float* gm = g_m + gr * HH + cb;
#pragma unroll
        for (int j = 0; j < 32; j += 4) {
            float4 o;
            o.x = silu_f(p[j + 0] + b2s[cb + j + 0]);
            o.y = silu_f(p[j + 1] + b2s[cb + j + 1]);
            o.z = silu_f(p[j + 2] + b2s[cb + j + 2]);
            o.w = silu_f(p[j + 3] + b2s[cb + j + 3]);
            *(float4*)(gm + j) = o;
            ((uint32_t*)p)[j + 0] = f2tf(o.x);
            ((uint32_t*)p)[j + 1] = f2tf(o.y);
            ((uint32_t*)p)[j + 2] = f2tf(o.z);
            ((uint32_t*)p)[j + 3] = f2tf(o.w);
        }
    }
    __syncthreads();

    // ---- stage 3: cw = silu(m @ Wc1 + b) . Wc2; coord atomics ----
    zero_c(c);
    issue_B(Wc1tf, 0, Bs0, tid); CP_COMMIT();
    issue_B(Wc1tf, 32, Bs1, tid); CP_COMMIT();
    for (int ch = 0; ch < 4; ch++) {
        if (ch == 3) cp_wait<0>(); else cp_wait<1>();
        __syncthreads();
        mma_chunk(c, T + ch * 32, LDT, (ch & 1) ? Bs1 : Bs0, wm, wn);
        __syncthreads();
        if (ch + 2 < 4) { issue_B(Wc1tf, (ch + 2) * 32, (ch & 1) ? Bs1 : Bs0, tid); CP_COMMIT(); }
    }
    store_c(c, T, wm, wn);
    __syncthreads();
    if (tid < TM) {
        const float* crow = T + tid * LDT;
        float cw = 0.f;
#pragma unroll 16
        for (int col = 0; col < 128; col++)
            cw += silu_f(crow[col] + bc1s[col]) * wc2s[col];
        long gr = row0 + tid;
        int b = (int)(gr / EE), e = (int)(gr - (long)b * EE);
        int s = bonds[2 * e], d = bonds[2 * e + 1];
        const float* cd = g_cdn + gr * 3;
#pragma unroll
        for (int cc = 0; cc < 3; cc++) {
            float u = cd[cc] * cw;
            atomicAdd(&g_cupd[((long)b * NN + d) * 3 + cc], u);
            atomicAdd(&g_cupd[((long)b * NN + s) * 3 + cc], -u);
        }
    }
}

// ---------------- fused node kernel ----------------------------------------
__global__ void __launch_bounds__(256, 3)
node_fused_k(const float* __restrict__ Wn1tf, const float* __restrict__ bn1,
             const float* __restrict__ Wn2tf, const float* __restrict__ bn2)
{
    extern __shared__ float dyn[];
    float* T   = dyn;
    float* Bs0 = dyn + TM * LDT;
    float* Bs1 = Bs0 + 32 * LDT;
    float* As0 = T;
    float* As1 = T + TM * LDAs;

    __shared__ float b1s[128], b2s[128];

    const int tid = threadIdx.x;
    const int wid = tid >> 5;
    const int wm = wid & 3, wn = wid >> 2;
    const long row0 = (long)blockIdx.x * TM;

    if (tid < 128) { b1s[tid] = bn1[tid]; b2s[tid] = bn2[tid]; }
    __syncthreads();

    const int arow = tid >> 2;
    const int akb  = (tid & 3) * 8;
    const long gra = row0 + arow;

    auto issue_A = [&](int ch, float* Asb) {
        int k0 = ch << 5;
        const float* src = ((k0 < 128) ? (g_htf + gra * HH) : (g_agg + gra * HH))
                           + (k0 & 127) + akb;
        uint32_t dst = s2u(Asb + arow * LDAs + akb);
        cp16(dst, src);
        cp16(dst + 16, src + 4);
    };

    FragC c[4];

    // ---- stage 1: n1 = silu([h|agg] @ Wn1 + b), K=256 ----
    zero_c(c);
    issue_A(0, As0); issue_B(Wn1tf, 0, Bs0, tid); CP_COMMIT();
    issue_A(1, As1); issue_B(Wn1tf, 32, Bs1, tid); CP_COMMIT();
    for (int ch = 0; ch < 8; ch++) {
        if (ch == 7) cp_wait<0>(); else cp_wait<1>();
        __syncthreads();
        mma_chunk(c, (ch & 1) ? As1 : As0, LDAs, (ch & 1) ? Bs1 : Bs0, wm, wn);
        __syncthreads();
        if (ch + 2 < 8) {
            issue_A(ch + 2, (ch & 1) ? As1 : As0);
            issue_B(Wn1tf, (ch + 2) * 32, (ch & 1) ? Bs1 : Bs0, tid);
            CP_COMMIT();
        }
    }
    store_c(c, T, wm, wn);
    __syncthreads();
    {
        const int row = tid >> 2, cb = (tid & 3) * 32;
        float* p = T + row * LDT + cb;
#pragma unroll
        for (int j = 0; j < 32; j++)
            ((uint32_t*)p)[j] = f2tf(silu_f(p[j] + b1s[cb + j]));
    }
    __syncthreads();

    // ---- stage 2: h += n1 @ Wn2 + b (also refresh g_htf) ----
    zero_c(c);
    issue_B(Wn2tf, 0, Bs0, tid); CP_COMMIT();
    issue_B(Wn2tf, 32, Bs1, tid); CP_COMMIT();
    for (int ch = 0; ch < 4; ch++) {
        if (ch == 3) cp_wait<0>(); else cp_wait<1>();
        __syncthreads();
        mma_chunk(c, T + ch * 32, LDT, (ch & 1) ? Bs1 : Bs0, wm, wn);
        __syncthreads();
        if (ch + 2 < 4) { issue_B(Wn2tf, (ch + 2) * 32, (ch & 1) ? Bs1 : Bs0, tid); CP_COMMIT(); }
    }
    store_c(c, T, wm, wn);
    __syncthreads();
    {
        const int row = tid >> 2, cb = (tid & 3) * 32;
        const long gr = row0 + row;
        const float* p = T + row * LDT + cb;
        float* hp = g_h + gr * HH + cb;
        float* htf = g_htf + gr * HH + cb;
#pragma unroll
        for (int j = 0; j < 32; j += 4) {
            float4 hv = *(const float4*)(hp + j);
            float4 o;
            o.x = hv.x + p[j + 0] + b2s[cb + j + 0];
            o.y = hv.y + p[j + 1] + b2s[cb + j + 1];
            o.z = hv.z + p[j + 2] + b2s[cb + j + 2];
            o.w = hv.w + p[j + 3] + b2s[cb + j + 3];
            *(float4*)(hp + j) = o;
            uint4 tf;
            tf.x = f2tf(o.x); tf.y = f2tf(o.y); tf.z = f2tf(o.z); tf.w = f2tf(o.w);
            *(uint4*)(htf + j) = tf;
        }
    }
}

// ---------------- fused output kernel --------------------------------------
__global__ void __launch_bounds__(256, 3)
out_fused_k(const float* __restrict__ Wo1tf, const float* __restrict__ bo1,
            const float* __restrict__ Wo2, const float* __restrict__ bo2,
            const float* __restrict__ x_in, float* __restrict__ out)
{
    extern __shared__ float dyn[];
    float* T   = dyn;
    float* Bs0 = dyn + TM * LDT;
    float* Bs1 = Bs0 + 32 * LDT;
    float* As0 = T;
    float* As1 = T + TM * LDAs;

    __shared__ float b1s[128];
    __shared__ float wo2s[128 * 3];

    const int tid = threadIdx.x;
    const int wid = tid >> 5;
    const int wm = wid & 3, wn = wid >> 2;
    const long row0 = (long)blockIdx.x * TM;

    if (tid < 128) b1s[tid] = bo1[tid];
    for (int i = tid; i < 384; i += 256) wo2s[i] = Wo2[i];
    __syncthreads();

    const int arow = tid >> 2;
    const int akb  = (tid & 3) * 8;
    const long gra = row0 + arow;

    auto issue_A = [&](int ch, float* Asb) {
        const float* src = g_htf + gra * HH + (ch << 5) + akb;
        uint32_t dst = s2u(Asb + arow * LDAs + akb);
        cp16(dst, src);
        cp16(dst + 16, src + 4);
    };

    FragC c[4];
    zero_c(c);
    issue_A(0, As0); issue_B(Wo1tf, 0, Bs0, tid); CP_COMMIT();
    issue_A(1, As1); issue_B(Wo1tf, 32, Bs1, tid); CP_COMMIT();
    for (int ch = 0; ch < 4; ch++) {
        if (ch == 3) cp_wait<0>(); else cp_wait<1>();
        __syncthreads();
        mma_chunk(c, (ch & 1) ? As1 : As0, LDAs, (ch & 1) ? Bs1 : Bs0, wm, wn);
        __syncthreads();
        if (ch + 2 < 4) {
            issue_A(ch + 2, (ch & 1) ? As1 : As0);
            issue_B(Wo1tf, (ch + 2) * 32, (ch & 1) ? Bs1 : Bs0, tid);
            CP_COMMIT();
        }
    }
    store_c(c, T, wm, wn);
    __syncthreads();
    if (tid < TM) {
        const float* crow = T + tid * LDT;
        float a0 = 0.f, a1 = 0.f, a2 = 0.f;
#pragma unroll 16
        for (int col = 0; col < 128; col++) {
            float v = silu_f(crow[col] + b1s[col]);
            a0 += v * wo2s[col * 3 + 0];
            a1 += v * wo2s[col * 3 + 1];
            a2 += v * wo2s[col * 3 + 2];
        }
        long base = (row0 + tid) * 3;
        out[base + 0] = a0 + bo2[0] + g_x[base + 0] - x_in[base + 0];
        out[base + 1] = a1 + bo2[1] + g_x[base + 1] - x_in[base + 1];
        out[base + 2] = a2 + bo2[2] + g_x[base + 2] - x_in[base + 2];
    }
}

// ---------------- setup kernels --------------------------------------------
__global__ void setupA_k(const float* __restrict__ t,
                         const float* __restrict__ W1, const float* __restrict__ b1,
                         const float* __restrict__ W2, const float* __restrict__ b2,
                         const float* __restrict__ emb,
                         const float* __restrict__ Wn, const float* __restrict__ bn,
                         const float* __restrict__ Wm1, const float* __restrict__ Wm2,
                         const float* __restrict__ Wc1, const float* __restrict__ Wn1,
                         const float* __restrict__ Wn2, const float* __restrict__ Wo1)
{
    const int tid = threadIdx.x;
    if (blockIdx.x == 0) {
        __shared__ float te[BB][TT];
        __shared__ float s1[BB][HH];
        const int half = TT / 2;
        for (int idx = tid; idx < BB * TT; idx += 256) {
            int b = idx / TT, k = idx % TT;
            int kk = (k < half) ? k : (k - half);
            float f = __expf((float)kk * (-logf(10000.f) / (float)(half - 1)));
            float a = t[b] * f;
            te[b][k] = (k < half) ? sinf(a) : cosf(a);
        }
        __syncthreads();
        if (tid < 128) {
            for (int b = 0; b < BB; b++) {
                float acc = b1[tid];
                for (int k = 0; k < TT; k++) acc += te[b][k] * W1[k * HH + tid];
                s1[b][tid] = silu_f(acc);
            }
        }
        __syncthreads();
        if (tid < 128) {
            for (int b = 0; b < BB; b++) {
                float acc = b2[tid];
                for (int k = 0; k < HH; k++) acc += s1[b][k] * W2[k * HH + tid];
                g_temb[b * HH + tid] = acc;
            }
        }
    } else if (blockIdx.x == 1) {
        for (int idx = tid; idx < 4 * HH; idx += 256) {
            int a = idx >> 7, j = idx & 127;
            float acc = bn[j];
            for (int k = 0; k < HH; k++) acc += emb[a * HH + k] * Wn[k * HH + j];
            g_table4[idx] = acc;
        }
    } else {
        long rid = (long)(blockIdx.x - 2) * 256 + tid;
        long rstride = (long)(gridDim.x - 2) * 256;
        for (long i = rid; i < 4L * 257 * 128; i += rstride) ((uint32_t*)g_wm1)[i] = f2tf(Wm1[i]);
        for (long i = rid; i < 4L * 128 * 128; i += rstride) ((uint32_t*)g_wm2)[i] = f2tf(Wm2[i]);
        for (long i = rid; i < 4L * 128 * 128; i += rstride) ((uint32_t*)g_wc1)[i] = f2tf(Wc1[i]);
        for (long i = rid; i < 4L * 256 * 128; i += rstride) ((uint32_t*)g_wn1)[i] = f2tf(Wn1[i]);
        for (long i = rid; i < 4L * 128 * 128; i += rstride) ((uint32_t*)g_wn2)[i] = f2tf(Wn2[i]);
        for (long i = rid; i < 128L * 128; i += rstride) ((uint32_t*)g_wo1)[i] = f2tf(Wo1[i]);
    }
}

__global__ void setupB_k(const int* __restrict__ types, const float* __restrict__ x,
                         const int* __restrict__ bonds)
{
    const long N1 = (long)BB * NN * HH;
    const long N2 = N1 + BB * NN * 3;
    const long N3 = N2 + BB * NN * 3;
    const long N4 = N3 + BB * EE;
    const long stride = (long)gridDim.x * 256;
    for (long idx = (long)blockIdx.x * 256 + threadIdx.x; idx < N4; idx += stride) {
        if (idx < N1) {
            int j = (int)(idx & 127);
            long bn = idx >> 7;
            int n = (int)(bn % NN), b = (int)(bn / NN);
            float v = g_table4[types[n] * HH + j] + g_temb[b * HH + j];
            g_h[idx] = v;
            ((uint32_t*)g_htf)[idx] = f2tf(v);
        } else if (idx < N2) {
            long i = idx - N1;
            g_x[i] = x[i];
        } else if (idx < N3) {
            g_cupd[idx - N2] = 0.f;
        } else {
            long i = idx - N3;
            int b = (int)(i / EE), e = (int)(i - (long)b * EE);
            int s = bonds[2 * e], d = bonds[2 * e + 1];
            const float* xs = x + ((long)b * NN + s) * 3;
            const float* xd = x + ((long)b * NN + d) * 3;
            float dx = xd[0] - xs[0], dy = xd[1] - xs[1], dz = xd[2] - xs[2];
            float dist = sqrtf(dx * dx + dy * dy + dz * dz);
            g_dist[i] = dist;
            float inv = 1.f / (dist + 1e-8f);
            g_cdn[i * 3 + 0] = dx * inv;
            g_cdn[i * 3 + 1] = dy * inv;
            g_cdn[i * 3 + 2] = dz * inv;
        }
    }
}

__global__ void prep_k(const int* __restrict__ bonds)
{
    const long N1 = (long)BB * NN * 3;
    const long N2 = N1 + BB * EE;
    const long stride = (long)gridDim.x * 256;
    for (long idx = (long)blockIdx.x * 256 + threadIdx.x; idx < N2; idx += stride) {
        if (idx < N1) {
            g_cupd[idx] = 0.f;
        } else {
            long i = idx - N1;
            int b = (int)(i / EE), e = (int)(i - (long)b * EE);
            int s = bonds[2 * e], d = bonds[2 * e + 1];
            const float* xs = g_x + ((long)b * NN + s) * 3;
            const float* xd = g_x + ((long)b * NN + d) * 3;
            float dx = xd[0] - xs[0], dy = xd[1] - xs[1], dz = xd[2] - xs[2];
            float dist = sqrtf(dx * dx + dy * dy + dz * dz);
            g_dist[i] = dist;
            float inv = 1.f / (dist + 1e-8f);
            g_cdn[i * 3 + 0] = dx * inv;
            g_cdn[i * 3 + 1] = dy * inv;
            g_cdn[i * 3 + 2] = dz * inv;
        }
    }
}

// ---------------- CSR + gather kernels --------------------------------------
__global__ void zero_i_k(int* __restrict__ p, int n)
{
    int idx = blockIdx.x * 256 + threadIdx.x;
    if (idx < n) p[idx] = 0;
}
__global__ void deg_count_k(const int* __restrict__ bonds)
{
    int e = blockIdx.x * 256 + threadIdx.x;
    if (e >= EE) return;
    atomicAdd(&g_deg[bonds[2 * e]], 1);
    atomicAdd(&g_deg[bonds[2 * e + 1]], 1);
}
__global__ void scan_k()
{
    __shared__ int sh[256];
    __shared__ int base;
    int tid = threadIdx.x;
    if (tid == 0) base = 0;
    __syncthreads();
    for (int i0 = 0; i0 < NN; i0 += 256) {
        int i = i0 + tid;
        int v = (i < NN) ? g_deg[i] : 0;
        sh[tid] = v;
        __syncthreads();
        for (int o = 1; o < 256; o <<= 1) {
            int t = (tid >= o) ? sh[tid - o] : 0;
            __syncthreads();
            sh[tid] += t;
            __syncthreads();
        }
        int excl = base + sh[tid] - v;
        if (i < NN) { g_off[i] = excl; g_cur[i] = excl; }
        __syncthreads();
        if (tid == 255) base += sh[255];
        __syncthreads();
    }
    if (tid == 0) g_off[NN] = base;
}
__global__ void fill_k(const int* __restrict__ bonds)
{
    int e = blockIdx.x * 256 + threadIdx.x;
    if (e >= EE) return;
    int s = bonds[2 * e], d = bonds[2 * e + 1];
    int p = atomicAdd(&g_cur[s], 1); g_csr[p] = e;
    int q = atomicAdd(&g_cur[d], 1); g_csr[q] = e;
}

__global__ void agg_gather_k()
{
    int warp = (blockIdx.x * 256 + threadIdx.x) >> 5;
    int lane = threadIdx.x & 31;
    if (warp >= BB * NN) return;
    int b = warp / NN, n = warp - b * NN;
    int o0 = g_off[n], o1 = g_off[n + 1];
    float4 acc = make_float4(0.f, 0.f, 0.f, 0.f);
    for (int j = o0; j < o1; j++) {
        int e = g_csr[j];
        float4 v = ((const float4*)(g_m + ((long)b * EE + e) * HH))[lane];
        acc.x += v.x; acc.y += v.y; acc.z += v.z; acc.w += v.w;
    }
    uint4 tf;
    tf.x = f2tf(acc.x); tf.y = f2tf(acc.y); tf.z = f2tf(acc.z); tf.w = f2tf(acc.w);
    ((uint4*)(g_agg + (long)warp * HH))[lane] = tf;
}

__global__ void x_update_k()
{
    int idx = blockIdx.x * 256 + threadIdx.x;
    if (idx >= BB * NN * 3) return;
    int n = (idx / 3) % NN;
    g_x[idx] += g_cupd[idx] / fmaxf((float)g_deg[n], 1.f);
}

// ---------------- launch ---------------------------------------------------
static inline int cdiv(long n, int b) { return (int)((n + b - 1) / b); }

extern "C" void kernel_launch(void* const* d_in, const int* in_sizes, int n_in,
                              void* d_out, int out_size)
{
    const float* x      = (const float*)d_in[0];
    const float* t      = (const float*)d_in[1];
    const int*   types  = (const int*)d_in[2];
    const int*   bonds  = (const int*)d_in[3];
    const float* emb    = (const float*)d_in[4];
    const float* W_t1   = (const float*)d_in[5];
    const float* b_t1   = (const float*)d_in[6];
    const float* W_t2   = (const float*)d_in[7];
    const float* b_t2   = (const float*)d_in[8];
    const float* W_node = (const float*)d_in[9];
    const float* b_node = (const float*)d_in[10];
    const float* Wm1    = (const float*)d_in[11];
    const float* bm1    = (const float*)d_in[12];
    const float* Wm2    = (const float*)d_in[13];
    const float* bm2    = (const float*)d_in[14];
    const float* Wn1    = (const float*)d_in[15];
    const float* bn1    = (const float*)d_in[16];
    const float* Wn2    = (const float*)d_in[17];
    const float* bn2    = (const float*)d_in[18];
    const float* Wc1    = (const float*)d_in[19];
    const float* bc1    = (const float*)d_in[20];
    const float* Wc2    = (const float*)d_in[21];
    const float* Wo1    = (const float*)d_in[22];
    const float* bo1    = (const float*)d_in[23];
    const float* Wo2    = (const float*)d_in[24];
    const float* bo2    = (const float*)d_in[25];
    float* out = (float*)d_out;

    float *p_wm1, *p_wm2, *p_wc1, *p_wn1, *p_wn2, *p_wo1;
    int *p_deg;
    cudaGetSymbolAddress((void**)&p_wm1, g_wm1);
    cudaGetSymbolAddress((void**)&p_wm2, g_wm2);
    cudaGetSymbolAddress((void**)&p_wc1, g_wc1);
    cudaGetSymbolAddress((void**)&p_wn1, g_wn1);
    cudaGetSymbolAddress((void**)&p_wn2, g_wn2);
    cudaGetSymbolAddress((void**)&p_wo1, g_wo1);
    cudaGetSymbolAddress((void**)&p_deg, g_deg);

    cudaFuncSetAttribute(edge_fused_k, cudaFuncAttributeMaxDynamicSharedMemorySize, FUSE_SMEM);
    cudaFuncSetAttribute(node_fused_k, cudaFuncAttributeMaxDynamicSharedMemorySize, FUSE_SMEM);
    cudaFuncSetAttribute(out_fused_k, cudaFuncAttributeMaxDynamicSharedMemorySize, FUSE_SMEM);

    const int gridE = BB * EE / TM;  // 5000
    const int gridN = BB * NN / TM;  // 2500

    setupA_k<<<194, 256>>>(t, W_t1, b_t1, W_t2, b_t2, emb, W_node, b_node,
                           Wm1, Wm2, Wc1, Wn1, Wn2, Wo1);
    setupB_k<<<4096, 256>>>(types, x, bonds);
    zero_i_k<<<cdiv(NN, 256), 256>>>(p_deg, NN);

    for (int l = 0; l < LL; l++) {
        if (l > 0) prep_k<<<2048, 256>>>(bonds);

        edge_fused_k<<<gridE, 256, FUSE_SMEM>>>(
            p_wm1 + (long)l * 257 * 128, bm1 + l * 128,
            Wm1 + ((long)l * 257 + 256) * 128,
            p_wm2 + (long)l * 16384, bm2 + l * 128,
            p_wc1 + (long)l * 16384, bc1 + l * 128, Wc2 + l * 128, bonds);

        if (l == 0) {
            deg_count_k<<<cdiv(EE, 256), 256>>>(bonds);
            scan_k<<<1, 256>>>();
            fill_k<<<cdiv(EE, 256), 256>>>(bonds);
        }

        agg_gather_k<<<cdiv((long)BB * NN * 32, 256), 256>>>();

        node_fused_k<<<gridN, 256, FUSE_SMEM>>>(
            p_wn1 + (long)l * 256 * 128, bn1 + l * 128,
            p_wn2 + (long)l * 16384, bn2 + l * 128);

        x_update_k<<<cdiv((long)BB * NN * 3, 256), 256>>>();
    }

    out_fused_k<<<gridN, 256, FUSE_SMEM>>>(p_wo1, bo1, Wo2, bo2, x, out);
}

// round 8
// speedup vs baseline: 1.0188x; 1.0188x over previous
#include <cuda_runtime.h>
#include <mma.h>
#include <math.h>
#include <stdint.h>

using namespace nvcuda;

#define BB 8
#define NN 20000
#define EE 40000
#define HH 128
#define TT 64
#define LL 4

__device__ __forceinline__ uint32_t f2tf(float f) {
    uint32_t u;
    asm("cvt.rna.tf32.f32 %0, %1;" : "=r"(u) : "f"(f));
    return u;
}
__device__ __forceinline__ float silu_f(float v) { return v / (1.f + __expf(-v)); }
__device__ __forceinline__ uint32_t s2u(const void* p) {
    uint32_t a;
    asm("{ .reg .u64 t; cvta.to.shared.u64 t, %1; cvt.u32.u64 %0, t; }" : "=r"(a) : "l"(p));
    return a;
}
__device__ __forceinline__ void cp16(uint32_t dst, const void* src) {
    asm volatile("cp.async.cg.shared.global [%0], [%1], 16;\n" :: "r"(dst), "l"(src));
}
#define CP_COMMIT() asm volatile("cp.async.commit_group;\n" ::: "memory")
template <int N> __device__ __forceinline__ void cp_wait() {
    asm volatile("cp.async.wait_group %0;\n" :: "n"(N) : "memory");
}

// ---------------- scratch (static device globals) --------------------------
__device__ float g_temb[BB * HH];
__device__ float g_table4[4 * HH];
__device__ float g_h[BB * NN * HH];
__device__ float g_htf[BB * NN * HH];    // tf32-rounded shadow of h
__device__ float g_agg[BB * NN * HH];    // tf32-rounded at store
__device__ float g_x[BB * NN * 3];
__device__ float g_cupd[BB * NN * 3];
__device__ float g_dist[BB * EE];
__device__ float g_cdn[BB * EE * 3];
__device__ float g_m[BB * EE * HH];
__device__ int   g_deg[NN];
__device__ int   g_off[NN + 1];
__device__ int   g_cur[NN];
__device__ int   g_csr[2 * EE];
// tf32-rounded weights
__device__ float g_wm1[4 * 257 * 128];
__device__ float g_wm2[4 * 128 * 128];
__device__ float g_wc1[4 * 128 * 128];
__device__ float g_wn1[4 * 256 * 128];
__device__ float g_wn2[4 * 128 * 128];
__device__ float g_wo1[128 * 128];

// ---------------- wmma helpers (M=128 tile, 512 thr, 4x4 warp grid) --------
#define LDT 136
#define LDAs 36
#define NTHR 512

using FragC = wmma::fragment<wmma::accumulator, 16, 16, 8, float>;
using FragA = wmma::fragment<wmma::matrix_a, 16, 16, 8, wmma::precision::tf32, wmma::row_major>;
using FragB = wmma::fragment<wmma::matrix_b, 16, 16, 8, wmma::precision::tf32, wmma::row_major>;

// warp wm (0..3): rows [wm*32,+32); warp wn (0..3): cols [wn*32,+32)
__device__ __forceinline__ void mma_chunk(FragC c[2][2], const float* Asrc, int lda,
                                          const float* Bs, int wm, int wn)
{
#pragma unroll
    for (int kk = 0; kk < 32; kk += 8) {
        FragA a[2];
        FragB b[2];
#pragma unroll
        for (int i = 0; i < 2; i++)
            wmma::load_matrix_sync(a[i], Asrc + (wm * 32 + i * 16) * lda + kk, lda);
#pragma unroll
        for (int j = 0; j < 2; j++)
            wmma::load_matrix_sync(b[j], Bs + kk * LDT + wn * 32 + j * 16, LDT);
#pragma unroll
        for (int i = 0; i < 2; i++)
#pragma unroll
            for (int j = 0; j < 2; j++)
                wmma::mma_sync(c[i][j], a[i], b[j], c[i][j]);
    }
}
__device__ __forceinline__ void zero_c(FragC c[2][2])
{
#pragma unroll
    for (int i = 0; i < 2; i++)
#pragma unroll
        for (int j = 0; j < 2; j++) wmma::fill_fragment(c[i][j], 0.f);
}
__device__ __forceinline__ void store_c(FragC c[2][2], float* T, int wm, int wn)
{
#pragma unroll
    for (int i = 0; i < 2; i++)
#pragma unroll
        for (int j = 0; j < 2; j++)
            wmma::store_matrix_sync(T + (wm * 32 + i * 16) * LDT + wn * 32 + j * 16,
                                    c[i][j], LDT, wmma::mem_row_major);
}

// one 32x128 B chunk via cp.async: 512 thr x 8 floats
__device__ __forceinline__ void issue_B(const float* __restrict__ W, int k0,
                                        float* Bsb, int tid)
{
    const int bkrow = tid >> 4;
    const int bnc   = (tid & 15) * 8;
    const float* src = W + (long)(k0 + bkrow) * 128 + bnc;
    uint32_t dst = s2u(Bsb + bkrow * LDT + bnc);
    cp16(dst, src);
    cp16(dst + 16, src + 4);
}

// dyn smem: T[128*LDT] + Bs0[32*LDT] + Bs1[32*LDT]; As ping-pong aliases T
#define FUSE_SMEM ((128 * LDT + 64 * LDT) * 4)   // 104448 B -> 2 CTAs/SM

// ---------------- fused edge kernel ----------------------------------------
__global__ void __launch_bounds__(NTHR, 2)
edge_fused_k(const float* __restrict__ Wm1tf, const float* __restrict__ bm1,
             const float* __restrict__ w256,
             const float* __restrict__ Wm2tf, const float* __restrict__ bm2,
             const float* __restrict__ Wc1tf, const float* __restrict__ bc1,
             const float* __restrict__ Wc2, const int* __restrict__ bonds)
{
    extern __shared__ float dyn[];
    float* T   = dyn;
    float* Bs0 = dyn + 128 * LDT;
    float* Bs1 = Bs0 + 32 * LDT;
    float* As0 = T;
    float* As1 = T + 128 * LDAs;

    __shared__ float b1s[128], b2s[128], bc1s[128], wc2s[128], wds[128];
    __shared__ const float* pA0[128];
    __shared__ const float* pA1[128];

    const int tid = threadIdx.x;
    const int wid = tid >> 5;
    const int wm = wid & 3, wn = wid >> 2;
    const long row0 = (long)blockIdx.x * 128;

    if (tid < 128) {
        b1s[tid] = bm1[tid]; b2s[tid] = bm2[tid];
        bc1s[tid] = bc1[tid]; wc2s[tid] = Wc2[tid]; wds[tid] = w256[tid];
        long gr = row0 + tid;
        int b = (int)(gr / EE), e = (int)(gr - (long)b * EE);
        int s = bonds[2 * e], d = bonds[2 * e + 1];
        pA0[tid] = g_htf + ((long)b * NN + s) * HH;
        pA1[tid] = g_htf + ((long)b * NN + d) * HH;
    }
    __syncthreads();

    const int arow = tid >> 2;          // 0..127
    const int akb  = (tid & 3) * 8;     // 2 cp16

    auto issue_A = [&](int ch, float* Asb) {
        int k0 = ch << 5;
        const float* src = ((k0 < 128) ? pA0[arow] : pA1[arow]) + (k0 & 127) + akb;
        uint32_t dst = s2u(Asb + arow * LDAs + akb);
        cp16(dst, src);
        cp16(dst + 16, src + 4);
    };

    FragC c[2][2];

    // ---- stage 1: m1 = silu(gather @ Wm1 + dist*w256 + b), K=256 ----
    zero_c(c);
    issue_A(0, As0); issue_B(Wm1tf, 0, Bs0, tid); CP_COMMIT();
    issue_A(1, As1); issue_B(Wm1tf, 32, Bs1, tid); CP_COMMIT();
    for (int ch = 0; ch < 8; ch++) {
        if (ch == 7) cp_wait<0>(); else cp_wait<1>();
        __syncthreads();
        mma_chunk(c, (ch & 1) ? As1 : As0, LDAs, (ch & 1) ? Bs1 : Bs0, wm, wn);
        __syncthreads();
        if (ch + 2 < 8) {
            issue_A(ch + 2, (ch & 1) ? As1 : As0);
            issue_B(Wm1tf, (ch + 2) * 32, (ch & 1) ? Bs1 : Bs0, tid);
            CP_COMMIT();
        }
    }
    store_c(c, T, wm, wn);
    __syncthreads();
    {
        const int row = tid >> 2, cb = (tid & 3) * 32;
        const float dv = g_dist[row0 + row];
        float* p = T + row * LDT + cb;
#pragma unroll
        for (int j = 0; j < 32; j++) {
            float v = silu_f(p[j] + b1s[cb + j] + dv * wds[cb + j]);
            ((uint32_t*)p)[j] = f2tf(v);
        }
    }
    __syncthreads();

    // ---- stage 2: m = silu(m1 @ Wm2 + b) ----
    zero_c(c);
    issue_B(Wm2tf, 0, Bs0, tid); CP_COMMIT();
    issue_B(Wm2tf, 32, Bs1, tid); CP_COMMIT();
    for (int ch = 0; ch < 4; ch++) {
        if (ch == 3) cp_wait<0>(); else cp_wait<1>();
        __syncthreads();
        mma_chunk(c, T + ch * 32, LDT, (ch & 1) ? Bs1 : Bs0, wm, wn);
        __syncthreads();
        if (ch + 2 < 4) { issue_B(Wm2tf, (ch + 2) * 32, (ch & 1) ? Bs1 : Bs0, tid); CP_COMMIT(); }
    }
    store_c(c, T, wm, wn);
    __syncthreads();
    {
        const int row = tid >> 2, cb = (tid & 3) * 32;
        const long gr = row0 + row;
        float* p = T + row * LDT + cb;
        float* gm = g_m + gr * HH + cb;
#pragma unroll
        for (int j = 0; j < 32; j += 4) {
            float4 o;
            o.x = silu_f(p[j + 0] + b2s[cb + j + 0]);
            o.y = silu_f(p[j + 1] + b2s[cb + j + 1]);
            o.z = silu_f(p[j + 2] + b2s[cb + j + 2]);
            o.w = silu_f(p[j + 3] + b2s[cb + j + 3]);
            *(float4*)(gm + j) = o;
            ((uint32_t*)p)[j + 0] = f2tf(o.x);
            ((uint32_t*)p)[j + 1] = f2tf(o.y);
            ((uint32_t*)p)[j + 2] = f2tf(o.z);
            ((uint32_t*)p)[j + 3] = f2tf(o.w);
        }
    }
    __syncthreads();

    // ---- stage 3: cw = silu(m @ Wc1 + b) . Wc2; coord atomics ----
    zero_c(c);
    issue_B(Wc1tf, 0, Bs0, tid); CP_COMMIT();
    issue_B(Wc1tf, 32, Bs1, tid); CP_COMMIT();
    for (int ch = 0; ch < 4; ch++) {
        if (ch == 3) cp_wait<0>(); else cp_wait<1>();
        __syncthreads();
        mma_chunk(c, T + ch * 32, LDT, (ch & 1) ? Bs1 : Bs0, wm, wn);
        __syncthreads();
        if (ch + 2 < 4) { issue_B(Wc1tf, (ch + 2) * 32, (ch & 1) ? Bs1 : Bs0, tid); CP_COMMIT(); }
    }
    store_c(c, T, wm, wn);
    __syncthreads();
    {
        const int row = tid >> 2, cb = (tid & 3) * 32;
        const float* crow = T + row * LDT + cb;
        float cw = 0.f;
#pragma unroll
        for (int j = 0; j < 32; j++)
            cw += silu_f(crow[j] + bc1s[cb + j]) * wc2s[cb + j];
        cw += __shfl_xor_sync(0xffffffffu, cw, 1);
        cw += __shfl_xor_sync(0xffffffffu, cw, 2);
        if ((tid & 3) == 0) {
            long gr = row0 + row;
            int b = (int)(gr / EE), e = (int)(gr - (long)b * EE);
            int s = bonds[2 * e], d = bonds[2 * e + 1];
            const float* cd = g_cdn + gr * 3;
#pragma unroll
            for (int cc = 0; cc < 3; cc++) {
                float u = cd[cc] * cw;
                atomicAdd(&g_cupd[((long)b * NN + d) * 3 + cc], u);
                atomicAdd(&g_cupd[((long)b * NN + s) * 3 + cc], -u);
            }
        }
    }
}

// ---------------- fused node kernel ----------------------------------------
__global__ void __launch_bounds__(NTHR, 2)
node_fused_k(const float* __restrict__ Wn1tf, const float* __restrict__ bn1,
             const float* __restrict__ Wn2tf, const float* __restrict__ bn2)
{
    extern __shared__ float dyn[];
    float* T   = dyn;
    float* Bs0 = dyn + 128 * LDT;
    float* Bs1 = Bs0 + 32 * LDT;
    float* As0 = T;
    float* As1 = T + 128 * LDAs;

    __shared__ float b1s[128], b2s[128];

    const int tid = threadIdx.x;
    const int wid = tid >> 5;
    const int wm = wid & 3, wn = wid >> 2;
    const long row0 = (long)blockIdx.x * 128;

    if (tid < 128) { b1s[tid] = bn1[tid]; b2s[tid] = bn2[tid]; }
    __syncthreads();

    const int arow = tid >> 2;
    const int akb  = (tid & 3) * 8;
    const long gra = row0 + arow;

    auto issue_A = [&](int ch, float* Asb) {
        int k0 = ch << 5;
        const float* src = ((k0 < 128) ? (g_htf + gra * HH) : (g_agg + gra * HH))
                           + (k0 & 127) + akb;
        uint32_t dst = s2u(Asb + arow * LDAs + akb);
        cp16(dst, src);
        cp16(dst + 16, src + 4);
    };

    FragC c[2][2];

    // ---- stage 1: n1 = silu([h|agg] @ Wn1 + b), K=256 ----
    zero_c(c);
    issue_A(0, As0); issue_B(Wn1tf, 0, Bs0, tid); CP_COMMIT();
    issue_A(1, As1); issue_B(Wn1tf, 32, Bs1, tid); CP_COMMIT();
    for (int ch = 0; ch < 8; ch++) {
        if (ch == 7) cp_wait<0>(); else cp_wait<1>();
        __syncthreads();
        mma_chunk(c, (ch & 1) ? As1 : As0, LDAs, (ch & 1) ? Bs1 : Bs0, wm, wn);
        __syncthreads();
        if (ch + 2 < 8) {
            issue_A(ch + 2, (ch & 1) ? As1 : As0);
            issue_B(Wn1tf, (ch + 2) * 32, (ch & 1) ? Bs1 : Bs0, tid);
            CP_COMMIT();
        }
    }
    store_c(c, T, wm, wn);
    __syncthreads();
    {
        const int row = tid >> 2, cb = (tid & 3) * 32;
        float* p = T + row * LDT + cb;
#pragma unroll
        for (int j = 0; j < 32; j++)
            ((uint32_t*)p)[j] = f2tf(silu_f(p[j] + b1s[cb + j]));
    }
    __syncthreads();

    // ---- stage 2: h += n1 @ Wn2 + b (also refresh g_htf) ----
    zero_c(c);
    issue_B(Wn2tf, 0, Bs0, tid); CP_COMMIT();
    issue_B(Wn2tf, 32, Bs1, tid); CP_COMMIT();
    for (int ch = 0; ch < 4; ch++) {
        if (ch == 3) cp_wait<0>(); else cp_wait<1>();
        __syncthreads();
        mma_chunk(c, T + ch * 32, LDT, (ch & 1) ? Bs1 : Bs0, wm, wn);
        __syncthreads();
        if (ch + 2 < 4) { issue_B(Wn2tf, (ch + 2) * 32, (ch & 1) ? Bs1 : Bs0, tid); CP_COMMIT(); }
    }
    store_c(c, T, wm, wn);
    __syncthreads();
    {
        const int row = tid >> 2, cb = (tid & 3) * 32;
        const long gr = row0 + row;
        const float* p = T + row * LDT + cb;
        float* hp = g_h + gr * HH + cb;
        float* htf = g_htf + gr * HH + cb;
#pragma unroll
        for (int j = 0; j < 32; j += 4) {
            float4 hv = *(const float4*)(hp + j);
            float4 o;
            o.x = hv.x + p[j + 0] + b2s[cb + j + 0];
            o.y = hv.y + p[j + 1] + b2s[cb + j + 1];
            o.z = hv.z + p[j + 2] + b2s[cb + j + 2];
            o.w = hv.w + p[j + 3] + b2s[cb + j + 3];
            *(float4*)(hp + j) = o;
            uint4 tf;
            tf.x = f2tf(o.x); tf.y = f2tf(o.y); tf.z = f2tf(o.z); tf.w = f2tf(o.w);
            *(uint4*)(htf + j) = tf;
        }
    }
}

// ---------------- fused output kernel --------------------------------------
__global__ void __launch_bounds__(NTHR, 2)
out_fused_k(const float* __restrict__ Wo1tf, const float* __restrict__ bo1,
            const float* __restrict__ Wo2, const float* __restrict__ bo2,
            const float* __restrict__ x_in, float* __restrict__ out)
{
    extern __shared__ float dyn[];
    float* T   = dyn;
    float* Bs0 = dyn + 128 * LDT;
    float* Bs1 = Bs0 + 32 * LDT;
    float* As0 = T;
    float* As1 = T + 128 * LDAs;

    __shared__ float b1s[128];
    __shared__ float wo2s[128 * 3];

    const int tid = threadIdx.x;
    const int wid = tid >> 5;
    const int wm = wid & 3, wn = wid >> 2;
    const long row0 = (long)blockIdx.x * 128;

    if (tid < 128) b1s[tid] = bo1[tid];
    if (tid >= 128 && tid < 512) { if (tid - 128 < 384) wo2s[tid - 128] = Wo2[tid - 128]; }
    __syncthreads();

    const int arow = tid >> 2;
    const int akb  = (tid & 3) * 8;
    const long gra = row0 + arow;

    auto issue_A = [&](int ch, float* Asb) {
        const float* src = g_htf + gra * HH + (ch << 5) + akb;
        uint32_t dst = s2u(Asb + arow * LDAs + akb);
        cp16(dst, src);
        cp16(dst + 16, src + 4);
    };

    FragC c[2][2];
    zero_c(c);
    issue_A(0, As0); issue_B(Wo1tf, 0, Bs0, tid); CP_COMMIT();
    issue_A(1, As1); issue_B(Wo1tf, 32, Bs1, tid); CP_COMMIT();
    for (int ch = 0; ch < 4; ch++) {
        if (ch == 3) cp_wait<0>(); else cp_wait<1>();
        __syncthreads();
        mma_chunk(c, (ch & 1) ? As1 : As0, LDAs, (ch & 1) ? Bs1 : Bs0, wm, wn);
        __syncthreads();
        if (ch + 2 < 4) {
            issue_A(ch + 2, (ch & 1) ? As1 : As0);
            issue_B(Wo1tf, (ch + 2) * 32, (ch & 1) ? Bs1 : Bs0, tid);
            CP_COMMIT();
        }
    }
    store_c(c, T, wm, wn);
    __syncthreads();
    {
        const int row = tid >> 2, cb = (tid & 3) * 32;
        const float* crow = T + row * LDT + cb;
        float a0 = 0.f, a1 = 0.f, a2 = 0.f;
#pragma unroll
        for (int j = 0; j < 32; j++) {
            float v = silu_f(crow[j] + b1s[cb + j]);
            a0 += v * wo2s[(cb + j) * 3 + 0];
            a1 += v * wo2s[(cb + j) * 3 + 1];
            a2 += v * wo2s[(cb + j) * 3 + 2];
        }
        a0 += __shfl_xor_sync(0xffffffffu, a0, 1);
        a0 += __shfl_xor_sync(0xffffffffu, a0, 2);
        a1 += __shfl_xor_sync(0xffffffffu, a1, 1);
        a1 += __shfl_xor_sync(0xffffffffu, a1, 2);
        a2 += __shfl_xor_sync(0xffffffffu, a2, 1);
        a2 += __shfl_xor_sync(0xffffffffu, a2, 2);
        if ((tid & 3) == 0) {
            long base = (row0 + row) * 3;
            out[base + 0] = a0 + bo2[0] + g_x[base + 0] - x_in[base + 0];
            out[base + 1] = a1 + bo2[1] + g_x[base + 1] - x_in[base + 1];
            out[base + 2] = a2 + bo2[2] + g_x[base + 2] - x_in[base + 2];
        }
    }
}

// ---------------- setup kernels --------------------------------------------
__global__ void setupA_k(const float* __restrict__ t,
                         const float* __restrict__ W1, const float* __restrict__ b1,
                         const float* __restrict__ W2, const float* __restrict__ b2,
                         const float* __restrict__ emb,
                         const float* __restrict__ Wn, const float* __restrict__ bn,
                         const float* __restrict__ Wm1, const float* __restrict__ Wm2,
                         const float* __restrict__ Wc1, const float* __restrict__ Wn1,
                         const float* __restrict__ Wn2, const float* __restrict__ Wo1)
{
    const int tid = threadIdx.x;
    if (blockIdx.x == 0) {
        __shared__ float te[BB][TT];
        __shared__ float s1[BB][HH];
        const int half = TT / 2;
        for (int idx = tid; idx < BB * TT; idx += 256) {
            int b = idx / TT, k = idx % TT;
            int kk = (k < half) ? k : (k - half);
            float f = __expf((float)kk * (-logf(10000.f) / (float)(half - 1)));
            float a = t[b] * f;
            te[b][k] = (k < half) ? sinf(a) : cosf(a);
        }
        __syncthreads();
        if (tid < 128) {
            for (int b = 0; b < BB; b++) {
                float acc = b1[tid];
                for (int k = 0; k < TT; k++) acc += te[b][k] * W1[k * HH + tid];
                s1[b][tid] = silu_f(acc);
            }
        }
        __syncthreads();
        if (tid < 128) {
            for (int b = 0; b < BB; b++) {
                float acc = b2[tid];
                for (int k = 0; k < HH; k++) acc += s1[b][k] * W2[k * HH + tid];
                g_temb[b * HH + tid] = acc;
            }
        }
    } else if (blockIdx.x == 1) {
        for (int idx = tid; idx < 4 * HH; idx += 256) {
            int a = idx >> 7, j = idx & 127;
            float acc = bn[j];
            for (int k = 0; k < HH; k++) acc += emb[a * HH + k] * Wn[k * HH + j];
            g_table4[idx] = acc;
        }
    } else {
        long rid = (long)(blockIdx.x - 2) * 256 + tid;
        long rstride = (long)(gridDim.x - 2) * 256;
        for (long i = rid; i < 4L * 257 * 128; i += rstride) ((uint32_t*)g_wm1)[i] = f2tf(Wm1[i]);
        for (long i = rid; i < 4L * 128 * 128; i += rstride) ((uint32_t*)g_wm2)[i] = f2tf(Wm2[i]);
        for (long i = rid; i < 4L * 128 * 128; i += rstride) ((uint32_t*)g_wc1)[i] = f2tf(Wc1[i]);
        for (long i = rid; i < 4L * 256 * 128; i += rstride) ((uint32_t*)g_wn1)[i] = f2tf(Wn1[i]);
        for (long i = rid; i < 4L * 128 * 128; i += rstride) ((uint32_t*)g_wn2)[i] = f2tf(Wn2[i]);
        for (long i = rid; i < 128L * 128; i += rstride) ((uint32_t*)g_wo1)[i] = f2tf(Wo1[i]);
    }
}

__global__ void setupB_k(const int* __restrict__ types, const float* __restrict__ x,
                         const int* __restrict__ bonds)
{
    const long N1 = (long)BB * NN * HH;
    const long N2 = N1 + BB * NN * 3;
    const long N3 = N2 + BB * NN * 3;
    const long N4 = N3 + BB * EE;
    const long stride = (long)gridDim.x * 256;
    for (long idx = (long)blockIdx.x * 256 + threadIdx.x; idx < N4; idx += stride) {
        if (idx < N1) {
            int j = (int)(idx & 127);
            long bn = idx >> 7;
            int n = (int)(bn % NN), b = (int)(bn / NN);
            float v = g_table4[types[n] * HH + j] + g_temb[b * HH + j];
            g_h[idx] = v;
            ((uint32_t*)g_htf)[idx] = f2tf(v);
        } else if (idx < N2) {
            long i = idx - N1;
            g_x[i] = x[i];
        } else if (idx < N3) {
            g_cupd[idx - N2] = 0.f;
        } else {
            long i = idx - N3;
            int b = (int)(i / EE), e = (int)(i - (long)b * EE);
            int s = bonds[2 * e], d = bonds[2 * e + 1];
            const float* xs = x + ((long)b * NN + s) * 3;
            const float* xd = x + ((long)b * NN + d) * 3;
            float dx = xd[0] - xs[0], dy = xd[1] - xs[1], dz = xd[2] - xs[2];
            float dist = sqrtf(dx * dx + dy * dy + dz * dz);
            g_dist[i] = dist;
            float inv = 1.f / (dist + 1e-8f);
            g_cdn[i * 3 + 0] = dx * inv;
            g_cdn[i * 3 + 1] = dy * inv;
            g_cdn[i * 3 + 2] = dz * inv;
        }
    }
}

__global__ void prep_k(const int* __restrict__ bonds)
{
    const long N1 = (long)BB * NN * 3;
    const long N2 = N1 + BB * EE;
    const long stride = (long)gridDim.x * 256;
    for (long idx = (long)blockIdx.x * 256 + threadIdx.x; idx < N2; idx += stride) {
        if (idx < N1) {
            g_cupd[idx] = 0.f;
        } else {
            long i = idx - N1;
            int b = (int)(i / EE), e = (int)(i - (long)b * EE);
            int s = bonds[2 * e], d = bonds[2 * e + 1];
            const float* xs = g_x + ((long)b * NN + s) * 3;
            const float* xd = g_x + ((long)b * NN + d) * 3;
            float dx = xd[0] - xs[0], dy = xd[1] - xs[1], dz = xd[2] - xs[2];
            float dist = sqrtf(dx * dx + dy * dy + dz * dz);
            g_dist[i] = dist;
            float inv = 1.f / (dist + 1e-8f);
            g_cdn[i * 3 + 0] = dx * inv;
            g_cdn[i * 3 + 1] = dy * inv;
            g_cdn[i * 3 + 2] = dz * inv;
        }
    }
}

// ---------------- CSR + gather kernels --------------------------------------
__global__ void zero_i_k(int* __restrict__ p, int n)
{
    int idx = blockIdx.x * 256 + threadIdx.x;
    if (idx < n) p[idx] = 0;
}
__global__ void deg_count_k(const int* __restrict__ bonds)
{
    int e = blockIdx.x * 256 + threadIdx.x;
    if (e >= EE) return;
    atomicAdd(&g_deg[bonds[2 * e]], 1);
    atomicAdd(&g_deg[bonds[2 * e + 1]], 1);
}
__global__ void scan_k()
{
    __shared__ int sh[256];
    __shared__ int base;
    int tid = threadIdx.x;
    if (tid == 0) base = 0;
    __syncthreads();
    for (int i0 = 0; i0 < NN; i0 += 256) {
        int i = i0 + tid;
        int v = (i < NN) ? g_deg[i] : 0;
        sh[tid] = v;
        __syncthreads();
        for (int o = 1; o < 256; o <<= 1) {
            int t = (tid >= o) ? sh[tid - o] : 0;
            __syncthreads();
            sh[tid] += t;
            __syncthreads();
        }
        int excl = base + sh[tid] - v;
        if (i < NN) { g_off[i] = excl; g_cur[i] = excl; }
        __syncthreads();
        if (tid == 255) base += sh[255];
        __syncthreads();
    }
    if (tid == 0) g_off[NN] = base;
}
__global__ void fill_k(const int* __restrict__ bonds)
{
    int e = blockIdx.x * 256 + threadIdx.x;
    if (e >= EE) return;
    int s = bonds[2 * e], d = bonds[2 * e + 1];
    int p = atomicAdd(&g_cur[s], 1); g_csr[p] = e;
    int q = atomicAdd(&g_cur[d], 1); g_csr[q] = e;
}

__global__ void agg_gather_k()
{
    int warp = (blockIdx.x * 256 + threadIdx.x) >> 5;
    int lane = threadIdx.x & 31;
    if (warp >= BB * NN) return;
    int b = warp / NN, n = warp - b * NN;
    int o0 = g_off[n], o1 = g_off[n + 1];
    float4 acc = make_float4(0.f, 0.f, 0.f, 0.f);
    for (int j = o0; j < o1; j++) {
        int e = g_csr[j];
        float4 v = ((const float4*)(g_m + ((long)b * EE + e) * HH))[lane];
        acc.x += v.x; acc.y += v.y; acc.z += v.z; acc.w += v.w;
    }
    uint4 tf;
    tf.x = f2tf(acc.x); tf.y = f2tf(acc.y); tf.z = f2tf(acc.z); tf.w = f2tf(acc.w);
    ((uint4*)(g_agg + (long)warp * HH))[lane] = tf;
}

__global__ void x_update_k()
{
    int idx = blockIdx.x * 256 + threadIdx.x;
    if (idx >= BB * NN * 3) return;
    int n = (idx / 3) % NN;
    g_x[idx] += g_cupd[idx] / fmaxf((float)g_deg[n], 1.f);
}

// ---------------- launch ---------------------------------------------------
static inline int cdiv(long n, int b) { return (int)((n + b - 1) / b); }

extern "C" void kernel_launch(void* const* d_in, const int* in_sizes, int n_in,
                              void* d_out, int out_size)
{
    const float* x      = (const float*)d_in[0];
    const float* t      = (const float*)d_in[1];
    const int*   types  = (const int*)d_in[2];
    const int*   bonds  = (const int*)d_in[3];
    const float* emb    = (const float*)d_in[4];
    const float* W_t1   = (const float*)d_in[5];
    const float* b_t1   = (const float*)d_in[6];
    const float* W_t2   = (const float*)d_in[7];
    const float* b_t2   = (const float*)d_in[8];
    const float* W_node = (const float*)d_in[9];
    const float* b_node = (const float*)d_in[10];
    const float* Wm1    = (const float*)d_in[11];
    const float* bm1    = (const float*)d_in[12];
    const float* Wm2    = (const float*)d_in[13];
    const float* bm2    = (const float*)d_in[14];
    const float* Wn1    = (const float*)d_in[15];
    const float* bn1    = (const float*)d_in[16];
    const float* Wn2    = (const float*)d_in[17];
    const float* bn2    = (const float*)d_in[18];
    const float* Wc1    = (const float*)d_in[19];
    const float* bc1    = (const float*)d_in[20];
    const float* Wc2    = (const float*)d_in[21];
    const float* Wo1    = (const float*)d_in[22];
    const float* bo1    = (const float*)d_in[23];
    const float* Wo2    = (const float*)d_in[24];
    const float* bo2    = (const float*)d_in[25];
    float* out = (float*)d_out;

    float *p_wm1, *p_wm2, *p_wc1, *p_wn1, *p_wn2, *p_wo1;
    int *p_deg;
    cudaGetSymbolAddress((void**)&p_wm1, g_wm1);
    cudaGetSymbolAddress((void**)&p_wm2, g_wm2);
    cudaGetSymbolAddress((void**)&p_wc1, g_wc1);
    cudaGetSymbolAddress((void**)&p_wn1, g_wn1);
    cudaGetSymbolAddress((void**)&p_wn2, g_wn2);
    cudaGetSymbolAddress((void**)&p_wo1, g_wo1);
    cudaGetSymbolAddress((void**)&p_deg, g_deg);

    cudaFuncSetAttribute(edge_fused_k, cudaFuncAttributeMaxDynamicSharedMemorySize, FUSE_SMEM);
    cudaFuncSetAttribute(node_fused_k, cudaFuncAttributeMaxDynamicSharedMemorySize, FUSE_SMEM);
    cudaFuncSetAttribute(out_fused_k, cudaFuncAttributeMaxDynamicSharedMemorySize, FUSE_SMEM);

    const int gridE = BB * EE / 128;  // 2500
    const int gridN = BB * NN / 128;  // 1250

    setupA_k<<<194, 256>>>(t, W_t1, b_t1, W_t2, b_t2, emb, W_node, b_node,
                           Wm1, Wm2, Wc1, Wn1, Wn2, Wo1);
    setupB_k<<<4096, 256>>>(types, x, bonds);
    zero_i_k<<<cdiv(NN, 256), 256>>>(p_deg, NN);

    for (int l = 0; l < LL; l++) {
        if (l > 0) prep_k<<<2048, 256>>>(bonds);

        edge_fused_k<<<gridE, NTHR, FUSE_SMEM>>>(
            p_wm1 + (long)l * 257 * 128, bm1 + l * 128,
            Wm1 + ((long)l * 257 + 256) * 128,
            p_wm2 + (long)l * 16384, bm2 + l * 128,
            p_wc1 + (long)l * 16384, bc1 + l * 128, Wc2 + l * 128, bonds);

        if (l == 0) {
            deg_count_k<<<cdiv(EE, 256), 256>>>(bonds);
            scan_k<<<1, 256>>>();
            fill_k<<<cdiv(EE, 256), 256>>>(bonds);
        }

        agg_gather_k<<<cdiv((long)BB * NN * 32, 256), 256>>>();

        node_fused_k<<<gridN, NTHR, FUSE_SMEM>>>(
            p_wn1 + (long)l * 256 * 128, bn1 + l * 128,
            p_wn2 + (long)l * 16384, bn2 + l * 128);

        x_update_k<<<cdiv((long)BB * NN * 3, 256), 256>>>();
    }

    out_fused_k<<<gridN, NTHR, FUSE_SMEM>>>(p_wo1, bo1, Wo2, bo2, x, out);
}

// round 9
// speedup vs baseline: 1.1769x; 1.1552x over previous
#include <cuda_runtime.h>
#include <mma.h>
#include <math.h>
#include <stdint.h>

using namespace nvcuda;

#define BB 8
#define NN 20000
#define EE 40000
#define HH 128
#define TT 64
#define LL 4

__device__ __forceinline__ uint32_t f2tf(float f) {
    uint32_t u;
    asm("cvt.rna.tf32.f32 %0, %1;" : "=r"(u) : "f"(f));
    return u;
}
__device__ __forceinline__ float silu_f(float v) { return v / (1.f + __expf(-v)); }
__device__ __forceinline__ uint32_t s2u(const void* p) {
    uint32_t a;
    asm("{ .reg .u64 t; cvta.to.shared.u64 t, %1; cvt.u32.u64 %0, t; }" : "=r"(a) : "l"(p));
    return a;
}
__device__ __forceinline__ void cp16(uint32_t dst, const void* src) {
    asm volatile("cp.async.cg.shared.global [%0], [%1], 16;\n" :: "r"(dst), "l"(src));
}
#define CP_COMMIT() asm volatile("cp.async.commit_group;\n" ::: "memory")
template <int N> __device__ __forceinline__ void cp_wait() {
    asm volatile("cp.async.wait_group %0;\n" :: "n"(N) : "memory");
}

// ---------------- scratch (static device globals) --------------------------
__device__ float g_temb[BB * HH];
__device__ float g_table4[4 * HH];
__device__ float g_h[BB * NN * HH];
__device__ float g_htf[BB * NN * HH];    // tf32-rounded shadow of h
__device__ float g_agg[BB * NN * HH];    // tf32-rounded at store
__device__ float g_x[BB * NN * 3];
__device__ float g_cupd[BB * NN * 3];
__device__ float g_dist[BB * EE];
__device__ float g_cdn[BB * EE * 3];
__device__ float g_m[BB * EE * HH];
__device__ int   g_deg[NN];
__device__ int   g_off[NN + 1];
__device__ int   g_cur[NN];
__device__ int   g_csr[2 * EE];
// tf32-rounded weights
__device__ float g_wm1[4 * 257 * 128];
__device__ float g_wm2[4 * 128 * 128];
__device__ float g_wc1[4 * 128 * 128];
__device__ float g_wn1[4 * 256 * 128];
__device__ float g_wn2[4 * 128 * 128];
__device__ float g_wo1[128 * 128];

// ---------------- wmma helpers (M=128 tile, 256 thr, 4x2 warp grid) --------
#define LDT 136
#define LDAs 36

using FragC = wmma::fragment<wmma::accumulator, 16, 16, 8, float>;
using FragA = wmma::fragment<wmma::matrix_a, 16, 16, 8, wmma::precision::tf32, wmma::row_major>;
using FragB = wmma::fragment<wmma::matrix_b, 16, 16, 8, wmma::precision::tf32, wmma::row_major>;

// warp wm (0..3): rows [wm*32,+32); warp wn (0..1): cols [wn*64,+64)
// B loaded DIRECTLY from global (pre-rounded weights, K-major [K][128])
__device__ __forceinline__ void mma_chunk_g(FragC c[2][4], const float* Asrc, int lda,
                                            const float* __restrict__ Wg, int k0,
                                            int wm, int wn)
{
#pragma unroll
    for (int kk = 0; kk < 32; kk += 8) {
        FragA a[2];
        FragB b[4];
#pragma unroll
        for (int i = 0; i < 2; i++)
            wmma::load_matrix_sync(a[i], Asrc + (wm * 32 + i * 16) * lda + kk, lda);
#pragma unroll
        for (int j = 0; j < 4; j++)
            wmma::load_matrix_sync(b[j], Wg + (long)(k0 + kk) * 128 + wn * 64 + j * 16, 128);
#pragma unroll
        for (int i = 0; i < 2; i++)
#pragma unroll
            for (int j = 0; j < 4; j++)
                wmma::mma_sync(c[i][j], a[i], b[j], c[i][j]);
    }
}
__device__ __forceinline__ void zero_c(FragC c[2][4])
{
#pragma unroll
    for (int i = 0; i < 2; i++)
#pragma unroll
        for (int j = 0; j < 4; j++) wmma::fill_fragment(c[i][j], 0.f);
}
__device__ __forceinline__ void store_c(FragC c[2][4], float* T, int wm, int wn)
{
#pragma unroll
    for (int i = 0; i < 2; i++)
#pragma unroll
        for (int j = 0; j < 4; j++)
            wmma::store_matrix_sync(T + (wm * 32 + i * 16) * LDT + wn * 64 + j * 16,
                                    c[i][j], LDT, wmma::mem_row_major);
}

// dyn smem: just T[128*LDT] (A staging buffers alias its front)
#define FUSE_SMEM (128 * LDT * 4)   // 69632 B -> 2 CTAs/SM (regs-bound)

// ---------------- fused edge kernel ----------------------------------------
__global__ void __launch_bounds__(256, 2)
edge_fused_k(const float* __restrict__ Wm1tf, const float* __restrict__ bm1,
             const float* __restrict__ w256,
             const float* __restrict__ Wm2tf, const float* __restrict__ bm2,
             const float* __restrict__ Wc1tf, const float* __restrict__ bc1,
             const float* __restrict__ Wc2, const int* __restrict__ bonds)
{
    extern __shared__ float dyn[];
    float* T = dyn;
    float* Ab[3] = { T, T + 128 * LDAs, T + 2 * 128 * LDAs };  // alias front of T

    __shared__ float b1s[128], b2s[128], bc1s[128], wc2s[128], wds[128];
    __shared__ const float* pA0[128];
    __shared__ const float* pA1[128];

    const int tid = threadIdx.x;
    const int wid = tid >> 5;
    const int wm = wid & 3, wn = wid >> 2;
    const long row0 = (long)blockIdx.x * 128;

    if (tid < 128) {
        b1s[tid] = bm1[tid]; b2s[tid] = bm2[tid];
        bc1s[tid] = bc1[tid]; wc2s[tid] = Wc2[tid]; wds[tid] = w256[tid];
        long gr = row0 + tid;
        int b = (int)(gr / EE), e = (int)(gr - (long)b * EE);
        int s = bonds[2 * e], d = bonds[2 * e + 1];
        pA0[tid] = g_htf + ((long)b * NN + s) * HH;
        pA1[tid] = g_htf + ((long)b * NN + d) * HH;
    }
    __syncthreads();

    const int arow = tid >> 1;
    const int akb  = (tid & 1) * 16;

    auto issue_A = [&](int ch, float* Asb) {
        int k0 = ch << 5;
        const float* src = ((k0 < 128) ? pA0[arow] : pA1[arow]) + (k0 & 127) + akb;
        uint32_t dst = s2u(Asb + arow * LDAs + akb);
#pragma unroll
        for (int q = 0; q < 4; q++) cp16(dst + q * 16, src + q * 4);
    };

    FragC c[2][4];

    // ---- stage 1: m1 = silu(gather @ Wm1 + dist*w256 + b), K=256 ----
    zero_c(c);
    issue_A(0, Ab[0]); CP_COMMIT();
    issue_A(1, Ab[1]); CP_COMMIT();
    for (int ch = 0; ch < 8; ch++) {
        if (ch == 7) cp_wait<0>(); else cp_wait<1>();
        __syncthreads();
        if (ch + 2 < 8) { issue_A(ch + 2, Ab[(ch + 2) % 3]); CP_COMMIT(); }
        mma_chunk_g(c, Ab[ch % 3], LDAs, Wm1tf, ch * 32, wm, wn);
    }
    __syncthreads();
    store_c(c, T, wm, wn);
    __syncthreads();
    {
        const int row = tid >> 1, cb = (tid & 1) * 64;
        const float dv = g_dist[row0 + row];
        float* p = T + row * LDT + cb;
#pragma unroll
        for (int j = 0; j < 64; j++) {
            float v = silu_f(p[j] + b1s[cb + j] + dv * wds[cb + j]);
            ((uint32_t*)p)[j] = f2tf(v);
        }
    }
    __syncthreads();

    // ---- stage 2: m = silu(m1 @ Wm2 + b) -- barrier-free K loop ----
    zero_c(c);
#pragma unroll
    for (int ch = 0; ch < 4; ch++)
        mma_chunk_g(c, T + ch * 32, LDT, Wm2tf, ch * 32, wm, wn);
    __syncthreads();
    store_c(c, T, wm, wn);
    __syncthreads();
    {
        const int row = tid >> 1, cb = (tid & 1) * 64;
        const long gr = row0 + row;
        float* p = T + row * LDT + cb;
        float* gm = g_m + gr * HH + cb;
#pragma unroll
        for (int j = 0; j < 64; j += 4) {
            float4 o;
            o.x = silu_f(p[j + 0] + b2s[cb + j + 0]);
            o.y = silu_f(p[j + 1] + b2s[cb + j + 1]);
            o.z = silu_f(p[j + 2] + b2s[cb + j + 2]);
            o.w = silu_f(p[j + 3] + b2s[cb + j + 3]);
            *(float4*)(gm + j) = o;
            ((uint32_t*)p)[j + 0] = f2tf(o.x);
            ((uint32_t*)p)[j + 1] = f2tf(o.y);
            ((uint32_t*)p)[j + 2] = f2tf(o.z);
            ((uint32_t*)p)[j + 3] = f2tf(o.w);
        }
    }
    __syncthreads();

    // ---- stage 3: cw = silu(m @ Wc1 + b) . Wc2; coord atomics ----
    zero_c(c);
#pragma unroll
    for (int ch = 0; ch < 4; ch++)
        mma_chunk_g(c, T + ch * 32, LDT, Wc1tf, ch * 32, wm, wn);
    __syncthreads();
    store_c(c, T, wm, wn);
    __syncthreads();
    if (tid < 128) {
        const float* crow = T + tid * LDT;
        float cw = 0.f;
#pragma unroll 16
        for (int col = 0; col < 128; col++)
            cw += silu_f(crow[col] + bc1s[col]) * wc2s[col];
        long gr = row0 + tid;
        int b = (int)(gr / EE), e = (int)(gr - (long)b * EE);
        int s = bonds[2 * e], d = bonds[2 * e + 1];
        const float* cd = g_cdn + gr * 3;
#pragma unroll
        for (int cc = 0; cc < 3; cc++) {
            float u = cd[cc] * cw;
            atomicAdd(&g_cupd[((long)b * NN + d) * 3 + cc], u);
            atomicAdd(&g_cupd[((long)b * NN + s) * 3 + cc], -u);
        }
    }
}

// ---------------- fused node kernel ----------------------------------------
__global__ void __launch_bounds__(256, 2)
node_fused_k(const float* __restrict__ Wn1tf, const float* __restrict__ bn1,
             const float* __restrict__ Wn2tf, const float* __restrict__ bn2)
{
    extern __shared__ float dyn[];
    float* T = dyn;
    float* Ab[3] = { T, T + 128 * LDAs, T + 2 * 128 * LDAs };

    __shared__ float b1s[128], b2s[128];

    const int tid = threadIdx.x;
    const int wid = tid >> 5;
    const int wm = wid & 3, wn = wid >> 2;
    const long row0 = (long)blockIdx.x * 128;

    if (tid < 128) { b1s[tid] = bn1[tid]; b2s[tid] = bn2[tid]; }
    __syncthreads();

    const int arow = tid >> 1;
    const int akb  = (tid & 1) * 16;
    const long gra = row0 + arow;

    auto issue_A = [&](int ch, float* Asb) {
        int k0 = ch << 5;
        const float* src = ((k0 < 128) ? (g_htf + gra * HH) : (g_agg + gra * HH))
                           + (k0 & 127) + akb;
        uint32_t dst = s2u(Asb + arow * LDAs + akb);
#pragma unroll
        for (int q = 0; q < 4; q++) cp16(dst + q * 16, src + q * 4);
    };

    FragC c[2][4];

    // ---- stage 1: n1 = silu([h|agg] @ Wn1 + b), K=256 ----
    zero_c(c);
    issue_A(0, Ab[0]); CP_COMMIT();
    issue_A(1, Ab[1]); CP_COMMIT();
    for (int ch = 0; ch < 8; ch++) {
        if (ch == 7) cp_wait<0>(); else cp_wait<1>();
        __syncthreads();
        if (ch + 2 < 8) { issue_A(ch + 2, Ab[(ch + 2) % 3]); CP_COMMIT(); }
        mma_chunk_g(c, Ab[ch % 3], LDAs, Wn1tf, ch * 32, wm, wn);
    }
    __syncthreads();
    store_c(c, T, wm, wn);
    __syncthreads();
    {
        const int row = tid >> 1, cb = (tid & 1) * 64;
        float* p = T + row * LDT + cb;
#pragma unroll
        for (int j = 0; j < 64; j++)
            ((uint32_t*)p)[j] = f2tf(silu_f(p[j] + b1s[cb + j]));
    }
    __syncthreads();

    // ---- stage 2: h += n1 @ Wn2 + b (also refresh g_htf) ----
    zero_c(c);
#pragma unroll
    for (int ch = 0; ch < 4; ch++)
        mma_chunk_g(c, T + ch * 32, LDT, Wn2tf, ch * 32, wm, wn);
    __syncthreads();
    store_c(c, T, wm, wn);
    __syncthreads();
    {
        const int row = tid >> 1, cb = (tid & 1) * 64;
        const long gr = row0 + row;
        const float* p = T + row * LDT + cb;
        float* hp = g_h + gr * HH + cb;
        float* htf = g_htf + gr * HH + cb;
#pragma unroll
        for (int j = 0; j < 64; j += 4) {
            float4 hv = *(const float4*)(hp + j);
            float4 o;
            o.x = hv.x + p[j + 0] + b2s[cb + j + 0];
            o.y = hv.y + p[j + 1] + b2s[cb + j + 1];
            o.z = hv.z + p[j + 2] + b2s[cb + j + 2];
            o.w = hv.w + p[j + 3] + b2s[cb + j + 3];
            *(float4*)(hp + j) = o;
            uint4 tf;
            tf.x = f2tf(o.x); tf.y = f2tf(o.y); tf.z = f2tf(o.z); tf.w = f2tf(o.w);
            *(uint4*)(htf + j) = tf;
        }
    }
}

// ---------------- fused output kernel --------------------------------------
__global__ void __launch_bounds__(256, 2)
out_fused_k(const float* __restrict__ Wo1tf, const float* __restrict__ bo1,
            const float* __restrict__ Wo2, const float* __restrict__ bo2,
            const float* __restrict__ x_in, float* __restrict__ out)
{
    extern __shared__ float dyn[];
    float* T = dyn;
    float* Ab[3] = { T, T + 128 * LDAs, T + 2 * 128 * LDAs };

    __shared__ float b1s[128];
    __shared__ float wo2s[128 * 3];

    const int tid = threadIdx.x;
    const int wid = tid >> 5;
    const int wm = wid & 3, wn = wid >> 2;
    const long row0 = (long)blockIdx.x * 128;

    if (tid < 128) b1s[tid] = bo1[tid];
    for (int i = tid; i < 384; i += 256) wo2s[i] = Wo2[i];
    __syncthreads();

    const int arow = tid >> 1;
    const int akb  = (tid & 1) * 16;
    const long gra = row0 + arow;

    auto issue_A = [&](int ch, float* Asb) {
        const float* src = g_htf + gra * HH + (ch << 5) + akb;
        uint32_t dst = s2u(Asb + arow * LDAs + akb);
#pragma unroll
        for (int q = 0; q < 4; q++) cp16(dst + q * 16, src + q * 4);
    };

    FragC c[2][4];
    zero_c(c);
    issue_A(0, Ab[0]); CP_COMMIT();
    issue_A(1, Ab[1]); CP_COMMIT();
    for (int ch = 0; ch < 4; ch++) {
        if (ch == 3) cp_wait<0>(); else cp_wait<1>();
        __syncthreads();
        if (ch + 2 < 4) { issue_A(ch + 2, Ab[(ch + 2) % 3]); CP_COMMIT(); }
        mma_chunk_g(c, Ab[ch % 3], LDAs, Wo1tf, ch * 32, wm, wn);
    }
    __syncthreads();
    store_c(c, T, wm, wn);
    __syncthreads();
    if (tid < 128) {
        const float* crow = T + tid * LDT;
        float a0 = 0.f, a1 = 0.f, a2 = 0.f;
#pragma unroll 16
        for (int col = 0; col < 128; col++) {
            float v = silu_f(crow[col] + b1s[col]);
            a0 += v * wo2s[col * 3 + 0];
            a1 += v * wo2s[col * 3 + 1];
            a2 += v * wo2s[col * 3 + 2];
        }
        long base = (row0 + tid) * 3;
        out[base + 0] = a0 + bo2[0] + g_x[base + 0] - x_in[base + 0];
        out[base + 1] = a1 + bo2[1] + g_x[base + 1] - x_in[base + 1];
        out[base + 2] = a2 + bo2[2] + g_x[base + 2] - x_in[base + 2];
    }
}

// ---------------- setup kernels --------------------------------------------
__global__ void setupA_k(const float* __restrict__ t,
                         const float* __restrict__ W1, const float* __restrict__ b1,
                         const float* __restrict__ W2, const float* __restrict__ b2,
                         const float* __restrict__ emb,
                         const float* __restrict__ Wn, const float* __restrict__ bn,
                         const float* __restrict__ Wm1, const float* __restrict__ Wm2,
                         const float* __restrict__ Wc1, const float* __restrict__ Wn1,
                         const float* __restrict__ Wn2, const float* __restrict__ Wo1)
{
    const int tid = threadIdx.x;
    if (blockIdx.x == 0) {
        __shared__ float te[BB][TT];
        __shared__ float s1[BB][HH];
        const int half = TT / 2;
        for (int idx = tid; idx < BB * TT; idx += 256) {
            int b = idx / TT, k = idx % TT;
            int kk = (k < half) ? k : (k - half);
            float f = __expf((float)kk * (-logf(10000.f) / (float)(half - 1)));
            float a = t[b] * f;
            te[b][k] = (k < half) ? sinf(a) : cosf(a);
        }
        __syncthreads();
        if (tid < 128) {
            for (int b = 0; b < BB; b++) {
                float acc = b1[tid];
                for (int k = 0; k < TT; k++) acc += te[b][k] * W1[k * HH + tid];
                s1[b][tid] = silu_f(acc);
            }
        }
        __syncthreads();
        if (tid < 128) {
            for (int b = 0; b < BB; b++) {
                float acc = b2[tid];
                for (int k = 0; k < HH; k++) acc += s1[b][k] * W2[k * HH + tid];
                g_temb[b * HH + tid] = acc;
            }
        }
    } else if (blockIdx.x == 1) {
        for (int idx = tid; idx < 4 * HH; idx += 256) {
            int a = idx >> 7, j = idx & 127;
            float acc = bn[j];
            for (int k = 0; k < HH; k++) acc += emb[a * HH + k] * Wn[k * HH + j];
            g_table4[idx] = acc;
        }
    } else {
        long rid = (long)(blockIdx.x - 2) * 256 + tid;
        long rstride = (long)(gridDim.x - 2) * 256;
        for (long i = rid; i < 4L * 257 * 128; i += rstride) ((uint32_t*)g_wm1)[i] = f2tf(Wm1[i]);
        for (long i = rid; i < 4L * 128 * 128; i += rstride) ((uint32_t*)g_wm2)[i] = f2tf(Wm2[i]);
        for (long i = rid; i < 4L * 128 * 128; i += rstride) ((uint32_t*)g_wc1)[i] = f2tf(Wc1[i]);
        for (long i = rid; i < 4L * 256 * 128; i += rstride) ((uint32_t*)g_wn1)[i] = f2tf(Wn1[i]);
        for (long i = rid; i < 4L * 128 * 128; i += rstride) ((uint32_t*)g_wn2)[i] = f2tf(Wn2[i]);
        for (long i = rid; i < 128L * 128; i += rstride) ((uint32_t*)g_wo1)[i] = f2tf(Wo1[i]);
    }
}

__global__ void setupB_k(const int* __restrict__ types, const float* __restrict__ x,
                         const int* __restrict__ bonds)
{
    const long N1 = (long)BB * NN * HH;
    const long N2 = N1 + BB * NN * 3;
    const long N3 = N2 + BB * NN * 3;
    const long N4 = N3 + BB * EE;
    const long stride = (long)gridDim.x * 256;
    for (long idx = (long)blockIdx.x * 256 + threadIdx.x; idx < N4; idx += stride) {
        if (idx < N1) {
            int j = (int)(idx & 127);
            long bn = idx >> 7;
            int n = (int)(bn % NN), b = (int)(bn / NN);
            float v = g_table4[types[n] * HH + j] + g_temb[b * HH + j];
            g_h[idx] = v;
            ((uint32_t*)g_htf)[idx] = f2tf(v);
        } else if (idx < N2) {
            long i = idx - N1;
            g_x[i] = x[i];
        } else if (idx < N3) {
            g_cupd[idx - N2] = 0.f;
        } else {
            long i = idx - N3;
            int b = (int)(i / EE), e = (int)(i - (long)b * EE);
            int s = bonds[2 * e], d = bonds[2 * e + 1];
            const float* xs = x + ((long)b * NN + s) * 3;
            const float* xd = x + ((long)b * NN + d) * 3;
            float dx = xd[0] - xs[0], dy = xd[1] - xs[1], dz = xd[2] - xs[2];
            float dist = sqrtf(dx * dx + dy * dy + dz * dz);
            g_dist[i] = dist;
            float inv = 1.f / (dist + 1e-8f);
            g_cdn[i * 3 + 0] = dx * inv;
            g_cdn[i * 3 + 1] = dy * inv;
            g_cdn[i * 3 + 2] = dz * inv;
        }
    }
}

__global__ void prep_k(const int* __restrict__ bonds)
{
    const long N1 = (long)BB * NN * 3;
    const long N2 = N1 + BB * EE;
    const long stride = (long)gridDim.x * 256;
    for (long idx = (long)blockIdx.x * 256 + threadIdx.x; idx < N2; idx += stride) {
        if (idx < N1) {
            g_cupd[idx] = 0.f;
        } else {
            long i = idx - N1;
            int b = (int)(i / EE), e = (int)(i - (long)b * EE);
            int s = bonds[2 * e], d = bonds[2 * e + 1];
            const float* xs = g_x + ((long)b * NN + s) * 3;
            const float* xd = g_x + ((long)b * NN + d) * 3;
            float dx = xd[0] - xs[0], dy = xd[1] - xs[1], dz = xd[2] - xs[2];
            float dist = sqrtf(dx * dx + dy * dy + dz * dz);
            g_dist[i] = dist;
            float inv = 1.f / (dist + 1e-8f);
            g_cdn[i * 3 + 0] = dx * inv;
            g_cdn[i * 3 + 1] = dy * inv;
            g_cdn[i * 3 + 2] = dz * inv;
        }
    }
}

// ---------------- CSR + gather kernels --------------------------------------
__global__ void zero_i_k(int* __restrict__ p, int n)
{
    int idx = blockIdx.x * 256 + threadIdx.x;
    if (idx < n) p[idx] = 0;
}
__global__ void deg_count_k(const int* __restrict__ bonds)
{
    int e = blockIdx.x * 256 + threadIdx.x;
    if (e >= EE) return;
    atomicAdd(&g_deg[bonds[2 * e]], 1);
    atomicAdd(&g_deg[bonds[2 * e + 1]], 1);
}
__global__ void scan_k()
{
    __shared__ int sh[256];
    __shared__ int base;
    int tid = threadIdx.x;
    if (tid == 0) base = 0;
    __syncthreads();
    for (int i0 = 0; i0 < NN; i0 += 256) {
        int i = i0 + tid;
        int v = (i < NN) ? g_deg[i] : 0;
        sh[tid] = v;
        __syncthreads();
        for (int o = 1; o < 256; o <<= 1) {
            int t = (tid >= o) ? sh[tid - o] : 0;
            __syncthreads();
            sh[tid] += t;
            __syncthreads();
        }
        int excl = base + sh[tid] - v;
        if (i < NN) { g_off[i] = excl; g_cur[i] = excl; }
        __syncthreads();
        if (tid == 255) base += sh[255];
        __syncthreads();
    }
    if (tid == 0) g_off[NN] = base;
}
__global__ void fill_k(const int* __restrict__ bonds)
{
    int e = blockIdx.x * 256 + threadIdx.x;
    if (e >= EE) return;
    int s = bonds[2 * e], d = bonds[2 * e + 1];
    int p = atomicAdd(&g_cur[s], 1); g_csr[p] = e;
    int q = atomicAdd(&g_cur[d], 1); g_csr[q] = e;
}

__global__ void agg_gather_k()
{
    int warp = (blockIdx.x * 256 + threadIdx.x) >> 5;
    int lane = threadIdx.x & 31;
    if (warp >= BB * NN) return;
    int b = warp / NN, n = warp - b * NN;
    int o0 = g_off[n], o1 = g_off[n + 1];
    float4 acc = make_float4(0.f, 0.f, 0.f, 0.f);
    for (int j = o0; j < o1; j++) {
        int e = g_csr[j];
        float4 v = ((const float4*)(g_m + ((long)b * EE + e) * HH))[lane];
        acc.x += v.x; acc.y += v.y; acc.z += v.z; acc.w += v.w;
    }
    uint4 tf;
    tf.x = f2tf(acc.x); tf.y = f2tf(acc.y); tf.z = f2tf(acc.z); tf.w = f2tf(acc.w);
    ((uint4*)(g_agg + (long)warp * HH))[lane] = tf;
}

__global__ void x_update_k()
{
    int idx = blockIdx.x * 256 + threadIdx.x;
    if (idx >= BB * NN * 3) return;
    int n = (idx / 3) % NN;
    g_x[idx] += g_cupd[idx] / fmaxf((float)g_deg[n], 1.f);
}

// ---------------- launch ---------------------------------------------------
static inline int cdiv(long n, int b) { return (int)((n + b - 1) / b); }

extern "C" void kernel_launch(void* const* d_in, const int* in_sizes, int n_in,
                              void* d_out, int out_size)
{
    const float* x      = (const float*)d_in[0];
    const float* t      = (const float*)d_in[1];
    const int*   types  = (const int*)d_in[2];
    const int*   bonds  = (const int*)d_in[3];
    const float* emb    = (const float*)d_in[4];
    const float* W_t1   = (const float*)d_in[5];
    const float* b_t1   = (const float*)d_in[6];
    const float* W_t2   = (const float*)d_in[7];
    const float* b_t2   = (const float*)d_in[8];
    const float* W_node = (const float*)d_in[9];
    const float* b_node = (const float*)d_in[10];
    const float* Wm1    = (const float*)d_in[11];
    const float* bm1    = (const float*)d_in[12];
    const float* Wm2    = (const float*)d_in[13];
    const float* bm2    = (const float*)d_in[14];
    const float* Wn1    = (const float*)d_in[15];
    const float* bn1    = (const float*)d_in[16];
    const float* Wn2    = (const float*)d_in[17];
    const float* bn2    = (const float*)d_in[18];
    const float* Wc1    = (const float*)d_in[19];
    const float* bc1    = (const float*)d_in[20];
    const float* Wc2    = (const float*)d_in[21];
    const float* Wo1    = (const float*)d_in[22];
    const float* bo1    = (const float*)d_in[23];
    const float* Wo2    = (const float*)d_in[24];
    const float* bo2    = (const float*)d_in[25];
    float* out = (float*)d_out;

    float *p_wm1, *p_wm2, *p_wc1, *p_wn1, *p_wn2, *p_wo1;
    int *p_deg;
    cudaGetSymbolAddress((void**)&p_wm1, g_wm1);
    cudaGetSymbolAddress((void**)&p_wm2, g_wm2);
    cudaGetSymbolAddress((void**)&p_wc1, g_wc1);
    cudaGetSymbolAddress((void**)&p_wn1, g_wn1);
    cudaGetSymbolAddress((void**)&p_wn2, g_wn2);
    cudaGetSymbolAddress((void**)&p_wo1, g_wo1);
    cudaGetSymbolAddress((void**)&p_deg, g_deg);

    cudaFuncSetAttribute(edge_fused_k, cudaFuncAttributeMaxDynamicSharedMemorySize, FUSE_SMEM);
    cudaFuncSetAttribute(node_fused_k, cudaFuncAttributeMaxDynamicSharedMemorySize, FUSE_SMEM);
    cudaFuncSetAttribute(out_fused_k, cudaFuncAttributeMaxDynamicSharedMemorySize, FUSE_SMEM);

    const int gridE = BB * EE / 128;  // 2500
    const int gridN = BB * NN / 128;  // 1250

    setupA_k<<<194, 256>>>(t, W_t1, b_t1, W_t2, b_t2, emb, W_node, b_node,
                           Wm1, Wm2, Wc1, Wn1, Wn2, Wo1);
    setupB_k<<<4096, 256>>>(types, x, bonds);
    zero_i_k<<<cdiv(NN, 256), 256>>>(p_deg, NN);

    for (int l = 0; l < LL; l++) {
        if (l > 0) prep_k<<<2048, 256>>>(bonds);

        edge_fused_k<<<gridE, 256, FUSE_SMEM>>>(
            p_wm1 + (long)l * 257 * 128, bm1 + l * 128,
            Wm1 + ((long)l * 257 + 256) * 128,
            p_wm2 + (long)l * 16384, bm2 + l * 128,
            p_wc1 + (long)l * 16384, bc1 + l * 128, Wc2 + l * 128, bonds);

        if (l == 0) {
            deg_count_k<<<cdiv(EE, 256), 256>>>(bonds);
            scan_k<<<1, 256>>>();
            fill_k<<<cdiv(EE, 256), 256>>>(bonds);
        }

        agg_gather_k<<<cdiv((long)BB * NN * 32, 256), 256>>>();

        node_fused_k<<<gridN, 256, FUSE_SMEM>>>(
            p_wn1 + (long)l * 256 * 128, bn1 + l * 128,
            p_wn2 + (long)l * 16384, bn2 + l * 128);

        x_update_k<<<cdiv((long)BB * NN * 3, 256), 256>>>();
    }

    out_fused_k<<<gridN, 256, FUSE_SMEM>>>(p_wo1, bo1, Wo2, bo2, x, out);
}

// round 10
// speedup vs baseline: 1.7007x; 1.4450x over previous
#include <cuda_runtime.h>
#include <mma.h>
#include <cuda_fp16.h>
#include <math.h>
#include <stdint.h>

using namespace nvcuda;

#define BB 8
#define NN 20000
#define EE 40000
#define HH 128
#define TT 64
#define LL 4

__device__ __forceinline__ float silu_f(float v) { return v / (1.f + __expf(-v)); }
__device__ __forceinline__ uint32_t s2u(const void* p) {
    uint32_t a;
    asm("{ .reg .u64 t; cvta.to.shared.u64 t, %1; cvt.u32.u64 %0, t; }" : "=r"(a) : "l"(p));
    return a;
}
__device__ __forceinline__ void cp16(uint32_t dst, const void* src) {
    asm volatile("cp.async.cg.shared.global [%0], [%1], 16;\n" :: "r"(dst), "l"(src));
}
#define CP_COMMIT() asm volatile("cp.async.commit_group;\n" ::: "memory")
template <int N> __device__ __forceinline__ void cp_wait() {
    asm volatile("cp.async.wait_group %0;\n" :: "n"(N) : "memory");
}

// ---------------- scratch (static device globals) --------------------------
__device__ float  g_temb[BB * HH];
__device__ float  g_table4[4 * HH];
__device__ float  g_h[BB * NN * HH];
__device__ __half g_htf[BB * NN * HH];   // fp16 shadow of h
__device__ __half g_agg[BB * NN * HH];   // fp16 (summed in fp32)
__device__ float  g_x[BB * NN * 3];
__device__ float  g_cupd[BB * NN * 3];
__device__ float  g_dist[BB * EE];
__device__ float  g_cdn[BB * EE * 3];
__device__ __half g_m[BB * EE * HH];     // fp16 messages
__device__ int    g_deg[NN];
__device__ int    g_off[NN + 1];
__device__ int    g_cur[NN];
__device__ int    g_csr[2 * EE];
// fp16 weights (K-major [K][128])
__device__ __half g_wm1[4 * 257 * 128];
__device__ __half g_wm2[4 * 128 * 128];
__device__ __half g_wc1[4 * 128 * 128];
__device__ __half g_wn1[4 * 256 * 128];
__device__ __half g_wn2[4 * 128 * 128];
__device__ __half g_wo1[128 * 128];

// ---------------- fp16 wmma config (M=128 tile, 256 thr, 4x2 warp grid) ----
#define LDTh 136   // halves
#define LDAh 40    // halves
#define LDBh 136   // halves

using FragC  = wmma::fragment<wmma::accumulator, 16, 16, 16, float>;
using FragAh = wmma::fragment<wmma::matrix_a, 16, 16, 16, __half, wmma::row_major>;
using FragBh = wmma::fragment<wmma::matrix_b, 16, 16, 16, __half, wmma::row_major>;

__device__ __forceinline__ void mma_chunk_h(FragC c[2][4], const __half* A, int lda,
                                            const __half* Bs, int wm, int wn)
{
#pragma unroll
    for (int kk = 0; kk < 32; kk += 16) {
        FragAh a[2];
        FragBh b[4];
#pragma unroll
        for (int i = 0; i < 2; i++)
            wmma::load_matrix_sync(a[i], A + (wm * 32 + i * 16) * lda + kk, lda);
#pragma unroll
        for (int j = 0; j < 4; j++)
            wmma::load_matrix_sync(b[j], Bs + kk * LDBh + wn * 64 + j * 16, LDBh);
#pragma unroll
        for (int i = 0; i < 2; i++)
#pragma unroll
            for (int j = 0; j < 4; j++)
                wmma::mma_sync(c[i][j], a[i], b[j], c[i][j]);
    }
}
__device__ __forceinline__ void zero_c(FragC c[2][4])
{
#pragma unroll
    for (int i = 0; i < 2; i++)
#pragma unroll
        for (int j = 0; j < 4; j++) wmma::fill_fragment(c[i][j], 0.f);
}

// drain accumulators through per-warp scratch with a fused elementwise fn:
// fn(r, colbase, ptr to 8 floats) ; element q is (row r, col colbase+q)
template <typename F>
__device__ __forceinline__ void epilogue_c(FragC c[2][4], float* swarp,
                                           int wm, int wn, int lane, F fn)
{
#pragma unroll
    for (int i = 0; i < 2; i++)
#pragma unroll
        for (int j = 0; j < 4; j++) {
            wmma::store_matrix_sync(swarp, c[i][j], 16, wmma::mem_row_major);
            __syncwarp();
            int r  = wm * 32 + i * 16 + (lane >> 1);
            int cb = wn * 64 + j * 16 + (lane & 1) * 8;
            fn(r, cb, swarp + lane * 8);
            __syncwarp();
        }
}

// B chunk (32 x 128 halves) via cp.async
__device__ __forceinline__ void issue_Bh(const __half* __restrict__ W, int k0,
                                         __half* Bsb, int tid)
{
    int row = tid >> 3;
    int off = (tid & 7) * 16;
    const __half* src = W + (long)(k0 + row) * 128 + off;
    uint32_t dst = s2u(Bsb + row * LDBh + off);
    cp16(dst, src);
    cp16(dst + 16, src + 8);
}

// dyn smem layout: Th[128*LDTh] | scratch[8*256 f32] | Bs0 | Bs1
#define OFF_SCR  34816
#define OFF_BS0  43008
#define OFF_BS1  51712
#define FUSE_SMEM 60416

// ---------------- fused edge kernel ----------------------------------------
__global__ void __launch_bounds__(256, 2)
edge_fused_k(const __half* __restrict__ Wm1h, const float* __restrict__ bm1,
             const float* __restrict__ w256,
             const __half* __restrict__ Wm2h, const float* __restrict__ bm2,
             const __half* __restrict__ Wc1h, const float* __restrict__ bc1,
             const float* __restrict__ Wc2, const int* __restrict__ bonds)
{
    extern __shared__ char dyn[];
    __half* Th  = (__half*)dyn;
    float*  scr = (float*)(dyn + OFF_SCR);
    __half* Bs0 = (__half*)(dyn + OFF_BS0);
    __half* Bs1 = (__half*)(dyn + OFF_BS1);
    __half* Ab0 = Th;                    // alias front of Th (dead in stage 1)
    __half* Ab1 = Th + 128 * LDAh;

    __shared__ float b1s[128], b2s[128], bc1s[128], wc2s[128], wds[128], dists[128];
    __shared__ float cwacc[128];
    __shared__ const __half* pA0[128];
    __shared__ const __half* pA1[128];

    const int tid = threadIdx.x;
    const int wid = tid >> 5, lane = tid & 31;
    const int wm = wid & 3, wn = wid >> 2;
    const long row0 = (long)blockIdx.x * 128;
    float* swarp = scr + wid * 256;

    if (tid < 128) {
        b1s[tid] = bm1[tid]; b2s[tid] = bm2[tid];
        bc1s[tid] = bc1[tid]; wc2s[tid] = Wc2[tid]; wds[tid] = w256[tid];
        dists[tid] = g_dist[row0 + tid];
        cwacc[tid] = 0.f;
        long gr = row0 + tid;
        int b = (int)(gr / EE), e = (int)(gr - (long)b * EE);
        int s = bonds[2 * e], d = bonds[2 * e + 1];
        pA0[tid] = g_htf + ((long)b * NN + s) * HH;
        pA1[tid] = g_htf + ((long)b * NN + d) * HH;
    }
    __syncthreads();

    const int arow = tid >> 1;
    const int aoff = (tid & 1) * 16;

    auto issue_A = [&](int ch, __half* Asb) {
        int k0 = ch << 5;
        const __half* src = ((k0 < 128) ? pA0[arow] : pA1[arow]) + (k0 & 127) + aoff;
        uint32_t dst = s2u(Asb + arow * LDAh + aoff);
        cp16(dst, src);
        cp16(dst + 16, src + 8);
    };

    FragC c[2][4];

    // ---- stage 1: m1 = silu(gather @ Wm1 + dist*w256 + b), K=256 ----
    zero_c(c);
    issue_A(0, Ab0); issue_Bh(Wm1h, 0, Bs0, tid); CP_COMMIT();
    issue_A(1, Ab1); issue_Bh(Wm1h, 32, Bs1, tid); CP_COMMIT();
    for (int ch = 0; ch < 8; ch++) {
        if (ch == 7) cp_wait<0>(); else cp_wait<1>();
        __syncthreads();
        mma_chunk_h(c, (ch & 1) ? Ab1 : Ab0, LDAh, (ch & 1) ? Bs1 : Bs0, wm, wn);
        __syncthreads();
        if (ch + 2 < 8) {
            issue_A(ch + 2, (ch & 1) ? Ab1 : Ab0);
            issue_Bh(Wm1h, (ch + 2) * 32, (ch & 1) ? Bs1 : Bs0, tid);
            CP_COMMIT();
        }
    }
    epilogue_c(c, swarp, wm, wn, lane, [&](int r, int cb, const float* v8) {
        float dv = dists[r];
#pragma unroll
        for (int q = 0; q < 8; q++) {
            int cc = cb + q;
            float v = silu_f(v8[q] + b1s[cc] + dv * wds[cc]);
            Th[r * LDTh + cc] = __float2half_rn(v);
        }
    });
    __syncthreads();

    // ---- stage 2: m = silu(m1 @ Wm2 + b) -> g_m (half) and Th ----
    zero_c(c);
    issue_Bh(Wm2h, 0, Bs0, tid); CP_COMMIT();
    issue_Bh(Wm2h, 32, Bs1, tid); CP_COMMIT();
    for (int ch = 0; ch < 4; ch++) {
        if (ch == 3) cp_wait<0>(); else cp_wait<1>();
        __syncthreads();
        mma_chunk_h(c, Th + ch * 32, LDTh, (ch & 1) ? Bs1 : Bs0, wm, wn);
        __syncthreads();
        if (ch + 2 < 4) { issue_Bh(Wm2h, (ch + 2) * 32, (ch & 1) ? Bs1 : Bs0, tid); CP_COMMIT(); }
    }
    epilogue_c(c, swarp, wm, wn, lane, [&](int r, int cb, const float* v8) {
        __half* gm = g_m + (row0 + r) * HH + cb;
#pragma unroll
        for (int q = 0; q < 8; q++) {
            int cc = cb + q;
            __half hv = __float2half_rn(silu_f(v8[q] + b2s[cc]));
            Th[r * LDTh + cc] = hv;
            gm[q] = hv;
        }
    });
    __syncthreads();

    // ---- stage 3: cw = silu(m @ Wc1 + b) . Wc2; coord atomics ----
    zero_c(c);
    issue_Bh(Wc1h, 0, Bs0, tid); CP_COMMIT();
    issue_Bh(Wc1h, 32, Bs1, tid); CP_COMMIT();
    for (int ch = 0; ch < 4; ch++) {
        if (ch == 3) cp_wait<0>(); else cp_wait<1>();
        __syncthreads();
        mma_chunk_h(c, Th + ch * 32, LDTh, (ch & 1) ? Bs1 : Bs0, wm, wn);
        __syncthreads();
        if (ch + 2 < 4) { issue_Bh(Wc1h, (ch + 2) * 32, (ch & 1) ? Bs1 : Bs0, tid); CP_COMMIT(); }
    }
    epilogue_c(c, swarp, wm, wn, lane, [&](int r, int cb, const float* v8) {
        float part = 0.f;
#pragma unroll
        for (int q = 0; q < 8; q++) {
            int cc = cb + q;
            part += silu_f(v8[q] + bc1s[cc]) * wc2s[cc];
        }
        atomicAdd(&cwacc[r], part);
    });
    __syncthreads();
    if (tid < 128) {
        float cw = cwacc[tid];
        long gr = row0 + tid;
        int b = (int)(gr / EE), e = (int)(gr - (long)b * EE);
        int s = bonds[2 * e], d = bonds[2 * e + 1];
        const float* cd = g_cdn + gr * 3;
#pragma unroll
        for (int cc = 0; cc < 3; cc++) {
            float u = cd[cc] * cw;
            atomicAdd(&g_cupd[((long)b * NN + d) * 3 + cc], u);
            atomicAdd(&g_cupd[((long)b * NN + s) * 3 + cc], -u);
        }
    }
}

// ---------------- fused node kernel ----------------------------------------
__global__ void __launch_bounds__(256, 2)
node_fused_k(const __half* __restrict__ Wn1h, const float* __restrict__ bn1,
             const __half* __restrict__ Wn2h, const float* __restrict__ bn2)
{
    extern __shared__ char dyn[];
    __half* Th  = (__half*)dyn;
    float*  scr = (float*)(dyn + OFF_SCR);
    __half* Bs0 = (__half*)(dyn + OFF_BS0);
    __half* Bs1 = (__half*)(dyn + OFF_BS1);
    __half* Ab0 = Th;
    __half* Ab1 = Th + 128 * LDAh;

    __shared__ float b1s[128], b2s[128];

    const int tid = threadIdx.x;
    const int wid = tid >> 5, lane = tid & 31;
    const int wm = wid & 3, wn = wid >> 2;
    const long row0 = (long)blockIdx.x * 128;
    float* swarp = scr + wid * 256;

    if (tid < 128) { b1s[tid] = bn1[tid]; b2s[tid] = bn2[tid]; }
    __syncthreads();

    const int arow = tid >> 1;
    const int aoff = (tid & 1) * 16;
    const long gra = row0 + arow;

    auto issue_A = [&](int ch, __half* Asb) {
        int k0 = ch << 5;
        const __half* src = ((k0 < 128) ? (g_htf + gra * HH) : (g_agg + gra * HH))
                            + (k0 & 127) + aoff;
        uint32_t dst = s2u(Asb + arow * LDAh + aoff);
        cp16(dst, src);
        cp16(dst + 16, src + 8);
    };

    FragC c[2][4];

    // ---- stage 1: n1 = silu([h|agg] @ Wn1 + b), K=256 ----
    zero_c(c);
    issue_A(0, Ab0); issue_Bh(Wn1h, 0, Bs0, tid); CP_COMMIT();
    issue_A(1, Ab1); issue_Bh(Wn1h, 32, Bs1, tid); CP_COMMIT();
    for (int ch = 0; ch < 8; ch++) {
        if (ch == 7) cp_wait<0>(); else cp_wait<1>();
        __syncthreads();
        mma_chunk_h(c, (ch & 1) ? Ab1 : Ab0, LDAh, (ch & 1) ? Bs1 : Bs0, wm, wn);
        __syncthreads();
        if (ch + 2 < 8) {
            issue_A(ch + 2, (ch & 1) ? Ab1 : Ab0);
            issue_Bh(Wn1h, (ch + 2) * 32, (ch & 1) ? Bs1 : Bs0, tid);
            CP_COMMIT();
        }
    }
    epilogue_c(c, swarp, wm, wn, lane, [&](int r, int cb, const float* v8) {
#pragma unroll
        for (int q = 0; q < 8; q++) {
            int cc = cb + q;
            Th[r * LDTh + cc] = __float2half_rn(silu_f(v8[q] + b1s[cc]));
        }
    });
    __syncthreads();

    // ---- stage 2: h += n1 @ Wn2 + b (refresh g_htf) ----
    zero_c(c);
    issue_Bh(Wn2h, 0, Bs0, tid); CP_COMMIT();
    issue_Bh(Wn2h, 32, Bs1, tid); CP_COMMIT();
    for (int ch = 0; ch < 4; ch++) {
        if (ch == 3) cp_wait<0>(); else cp_wait<1>();
        __syncthreads();
        mma_chunk_h(c, Th + ch * 32, LDTh, (ch & 1) ? Bs1 : Bs0, wm, wn);
        __syncthreads();
        if (ch + 2 < 4) { issue_Bh(Wn2h, (ch + 2) * 32, (ch & 1) ? Bs1 : Bs0, tid); CP_COMMIT(); }
    }
    epilogue_c(c, swarp, wm, wn, lane, [&](int r, int cb, const float* v8) {
        long base = (row0 + r) * HH + cb;
#pragma unroll
        for (int q = 0; q < 8; q++) {
            int cc = cb + q;
            float o = g_h[base + q] + v8[q] + b2s[cc];
            g_h[base + q] = o;
            g_htf[base + q] = __float2half_rn(o);
        }
    });
}

// ---------------- fused output kernel --------------------------------------
__global__ void __launch_bounds__(256, 2)
out_fused_k(const __half* __restrict__ Wo1h, const float* __restrict__ bo1,
            const float* __restrict__ Wo2, const float* __restrict__ bo2,
            const float* __restrict__ x_in, float* __restrict__ out)
{
    extern __shared__ char dyn[];
    __half* Th  = (__half*)dyn;
    float*  scr = (float*)(dyn + OFF_SCR);
    __half* Bs0 = (__half*)(dyn + OFF_BS0);
    __half* Bs1 = (__half*)(dyn + OFF_BS1);
    __half* Ab0 = Th;
    __half* Ab1 = Th + 128 * LDAh;

    __shared__ float b1s[128];
    __shared__ float wo2s[128 * 3];
    __shared__ float oacc[128 * 3];

    const int tid = threadIdx.x;
    const int wid = tid >> 5, lane = tid & 31;
    const int wm = wid & 3, wn = wid >> 2;
    const long row0 = (long)blockIdx.x * 128;
    float* swarp = scr + wid * 256;

    if (tid < 128) b1s[tid] = bo1[tid];
    for (int i = tid; i < 384; i += 256) { wo2s[i] = Wo2[i]; oacc[i] = 0.f; }
    __syncthreads();

    const int arow = tid >> 1;
    const int aoff = (tid & 1) * 16;
    const long gra = row0 + arow;

    auto issue_A = [&](int ch, __half* Asb) {
        const __half* src = g_htf + gra * HH + (ch << 5) + aoff;
        uint32_t dst = s2u(Asb + arow * LDAh + aoff);
        cp16(dst, src);
        cp16(dst + 16, src + 8);
    };

    FragC c[2][4];
    zero_c(c);
    issue_A(0, Ab0); issue_Bh(Wo1h, 0, Bs0, tid); CP_COMMIT();
    issue_A(1, Ab1); issue_Bh(Wo1h, 32, Bs1, tid); CP_COMMIT();
    for (int ch = 0; ch < 4; ch++) {
        if (ch == 3) cp_wait<0>(); else cp_wait<1>();
        __syncthreads();
        mma_chunk_h(c, (ch & 1) ? Ab1 : Ab0, LDAh, (ch & 1) ? Bs1 : Bs0, wm, wn);
        __syncthreads();
        if (ch + 2 < 4) {
            issue_A(ch + 2, (ch & 1) ? Ab1 : Ab0);
            issue_Bh(Wo1h, (ch + 2) * 32, (ch & 1) ? Bs1 : Bs0, tid);
            CP_COMMIT();
        }
    }
    epilogue_c(c, swarp, wm, wn, lane, [&](int r, int cb, const float* v8) {
        float a0 = 0.f, a1 = 0.f, a2 = 0.f;
#pragma unroll
        for (int q = 0; q < 8; q++) {
            int cc = cb + q;
            float v = silu_f(v8[q] + b1s[cc]);
            a0 += v * wo2s[cc * 3 + 0];
            a1 += v * wo2s[cc * 3 + 1];
            a2 += v * wo2s[cc * 3 + 2];
        }
        atomicAdd(&oacc[r * 3 + 0], a0);
        atomicAdd(&oacc[r * 3 + 1], a1);
        atomicAdd(&oacc[r * 3 + 2], a2);
    });
    __syncthreads();
    if (tid < 128) {
        long base = (row0 + tid) * 3;
#pragma unroll
        for (int cc = 0; cc < 3; cc++)
            out[base + cc] = oacc[tid * 3 + cc] + bo2[cc] + g_x[base + cc] - x_in[base + cc];
    }
}

// ---------------- setup kernels --------------------------------------------
__global__ void setupA_k(const float* __restrict__ t,
                         const float* __restrict__ W1, const float* __restrict__ b1,
                         const float* __restrict__ W2, const float* __restrict__ b2,
                         const float* __restrict__ emb,
                         const float* __restrict__ Wn, const float* __restrict__ bn,
                         const float* __restrict__ Wm1, const float* __restrict__ Wm2,
                         const float* __restrict__ Wc1, const float* __restrict__ Wn1,
                         const float* __restrict__ Wn2, const float* __restrict__ Wo1)
{
    const int tid = threadIdx.x;
    if (blockIdx.x == 0) {
        __shared__ float te[BB][TT];
        __shared__ float s1[BB][HH];
        const int half = TT / 2;
        for (int idx = tid; idx < BB * TT; idx += 256) {
            int b = idx / TT, k = idx % TT;
            int kk = (k < half) ? k : (k - half);
            float f = __expf((float)kk * (-logf(10000.f) / (float)(half - 1)));
            float a = t[b] * f;
            te[b][k] = (k < half) ? sinf(a) : cosf(a);
        }
        __syncthreads();
        if (tid < 128) {
            for (int b = 0; b < BB; b++) {
                float acc = b1[tid];
                for (int k = 0; k < TT; k++) acc += te[b][k] * W1[k * HH + tid];
                s1[b][tid] = silu_f(acc);
            }
        }
        __syncthreads();
        if (tid < 128) {
            for (int b = 0; b < BB; b++) {
                float acc = b2[tid];
                for (int k = 0; k < HH; k++) acc += s1[b][k] * W2[k * HH + tid];
                g_temb[b * HH + tid] = acc;
            }
        }
    } else if (blockIdx.x == 1) {
        for (int idx = tid; idx < 4 * HH; idx += 256) {
            int a = idx >> 7, j = idx & 127;
            float acc = bn[j];
            for (int k = 0; k < HH; k++) acc += emb[a * HH + k] * Wn[k * HH + j];
            g_table4[idx] = acc;
        }
    } else {
        long rid = (long)(blockIdx.x - 2) * 256 + tid;
        long rstride = (long)(gridDim.x - 2) * 256;
        for (long i = rid; i < 4L * 257 * 128; i += rstride) g_wm1[i] = __float2half_rn(Wm1[i]);
        for (long i = rid; i < 4L * 128 * 128; i += rstride) g_wm2[i] = __float2half_rn(Wm2[i]);
        for (long i = rid; i < 4L * 128 * 128; i += rstride) g_wc1[i] = __float2half_rn(Wc1[i]);
        for (long i = rid; i < 4L * 256 * 128; i += rstride) g_wn1[i] = __float2half_rn(Wn1[i]);
        for (long i = rid; i < 4L * 128 * 128; i += rstride) g_wn2[i] = __float2half_rn(Wn2[i]);
        for (long i = rid; i < 128L * 128; i += rstride)     g_wo1[i] = __float2half_rn(Wo1[i]);
    }
}

__global__ void setupB_k(const int* __restrict__ types, const float* __restrict__ x,
                         const int* __restrict__ bonds)
{
    const long N1 = (long)BB * NN * HH;
    const long N2 = N1 + BB * NN * 3;
    const long N3 = N2 + BB * NN * 3;
    const long N4 = N3 + BB * EE;
    const long stride = (long)gridDim.x * 256;
    for (long idx = (long)blockIdx.x * 256 + threadIdx.x; idx < N4; idx += stride) {
        if (idx < N1) {
            int j = (int)(idx & 127);
            long bn = idx >> 7;
            int n = (int)(bn % NN), b = (int)(bn / NN);
            float v = g_table4[types[n] * HH + j] + g_temb[b * HH + j];
            g_h[idx] = v;
            g_htf[idx] = __float2half_rn(v);
        } else if (idx < N2) {
            long i = idx - N1;
            g_x[i] = x[i];
        } else if (idx < N3) {
            g_cupd[idx - N2] = 0.f;
        } else {
            long i = idx - N3;
            int b = (int)(i / EE), e = (int)(i - (long)b * EE);
            int s = bonds[2 * e], d = bonds[2 * e + 1];
            const float* xs = x + ((long)b * NN + s) * 3;
            const float* xd = x + ((long)b * NN + d) * 3;
            float dx = xd[0] - xs[0], dy = xd[1] - xs[1], dz = xd[2] - xs[2];
            float dist = sqrtf(dx * dx + dy * dy + dz * dz);
            g_dist[i] = dist;
            float inv = 1.f / (dist + 1e-8f);
            g_cdn[i * 3 + 0] = dx * inv;
            g_cdn[i * 3 + 1] = dy * inv;
            g_cdn[i * 3 + 2] = dz * inv;
        }
    }
}

__global__ void prep_k(const int* __restrict__ bonds)
{
    const long N1 = (long)BB * NN * 3;
    const long N2 = N1 + BB * EE;
    const long stride = (long)gridDim.x * 256;
    for (long idx = (long)blockIdx.x * 256 + threadIdx.x; idx < N2; idx += stride) {
        if (idx < N1) {
            g_cupd[idx] = 0.f;
        } else {
            long i = idx - N1;
            int b = (int)(i / EE), e = (int)(i - (long)b * EE);
            int s = bonds[2 * e], d = bonds[2 * e + 1];
            const float* xs = g_x + ((long)b * NN + s) * 3;
            const float* xd = g_x + ((long)b * NN + d) * 3;
            float dx = xd[0] - xs[0], dy = xd[1] - xs[1], dz = xd[2] - xs[2];
            float dist = sqrtf(dx * dx + dy * dy + dz * dz);
            g_dist[i] = dist;
            float inv = 1.f / (dist + 1e-8f);
            g_cdn[i * 3 + 0] = dx * inv;
            g_cdn[i * 3 + 1] = dy * inv;
            g_cdn[i * 3 + 2] = dz * inv;
        }
    }
}

// ---------------- CSR + gather kernels --------------------------------------
__global__ void zero_i_k(int* __restrict__ p, int n)
{
    int idx = blockIdx.x * 256 + threadIdx.x;
    if (idx < n) p[idx] = 0;
}
__global__ void deg_count_k(const int* __restrict__ bonds)
{
    int e = blockIdx.x * 256 + threadIdx.x;
    if (e >= EE) return;
    atomicAdd(&g_deg[bonds[2 * e]], 1);
    atomicAdd(&g_deg[bonds[2 * e + 1]], 1);
}
__global__ void scan_k()
{
    __shared__ int sh[256];
    __shared__ int base;
    int tid = threadIdx.x;
    if (tid == 0) base = 0;
    __syncthreads();
    for (int i0 = 0; i0 < NN; i0 += 256) {
        int i = i0 + tid;
        int v = (i < NN) ? g_deg[i] : 0;
        sh[tid] = v;
        __syncthreads();
        for (int o = 1; o < 256; o <<= 1) {
            int t = (tid >= o) ? sh[tid - o] : 0;
            __syncthreads();
            sh[tid] += t;
            __syncthreads();
        }
        int excl = base + sh[tid] - v;
        if (i < NN) { g_off[i] = excl; g_cur[i] = excl; }
        __syncthreads();
        if (tid == 255) base += sh[255];
        __syncthreads();
    }
    if (tid == 0) g_off[NN] = base;
}
__global__ void fill_k(const int* __restrict__ bonds)
{
    int e = blockIdx.x * 256 + threadIdx.x;
    if (e >= EE) return;
    int s = bonds[2 * e], d = bonds[2 * e + 1];
    int p = atomicAdd(&g_cur[s], 1); g_csr[p] = e;
    int q = atomicAdd(&g_cur[d], 1); g_csr[q] = e;
}

// agg[b,n,:] = sum of m (half) over incident edges, fp32 accum, half store
__global__ void agg_gather_k()
{
    int warp = (blockIdx.x * 256 + threadIdx.x) >> 5;
    int lane = threadIdx.x & 31;
    if (warp >= BB * NN) return;
    int b = warp / NN, n = warp - b * NN;
    int o0 = g_off[n], o1 = g_off[n + 1];
    float acc[4] = {0.f, 0.f, 0.f, 0.f};
    for (int j = o0; j < o1; j++) {
        int e = g_csr[j];
        const __half2* row = (const __half2*)(g_m + ((long)b * EE + e) * HH) + lane * 2;
        float2 v0 = __half22float2(row[0]);
        float2 v1 = __half22float2(row[1]);
        acc[0] += v0.x; acc[1] += v0.y; acc[2] += v1.x; acc[3] += v1.y;
    }
    __half2* dst = (__half2*)(g_agg + (long)warp * HH) + lane * 2;
    dst[0] = __floats2half2_rn(acc[0], acc[1]);
    dst[1] = __floats2half2_rn(acc[2], acc[3]);
}

__global__ void x_update_k()
{
    int idx = blockIdx.x * 256 + threadIdx.x;
    if (idx >= BB * NN * 3) return;
    int n = (idx / 3) % NN;
    g_x[idx] += g_cupd[idx] / fmaxf((float)g_deg[n], 1.f);
}

// ---------------- launch ---------------------------------------------------
static inline int cdiv(long n, int b) { return (int)((n + b - 1) / b); }

extern "C" void kernel_launch(void* const* d_in, const int* in_sizes, int n_in,
                              void* d_out, int out_size)
{
    const float* x      = (const float*)d_in[0];
    const float* t      = (const float*)d_in[1];
    const int*   types  = (const int*)d_in[2];
    const int*   bonds  = (const int*)d_in[3];
    const float* emb    = (const float*)d_in[4];
    const float* W_t1   = (const float*)d_in[5];
    const float* b_t1   = (const float*)d_in[6];
    const float* W_t2   = (const float*)d_in[7];
    const float* b_t2   = (const float*)d_in[8];
    const float* W_node = (const float*)d_in[9];
    const float* b_node = (const float*)d_in[10];
    const float* Wm1    = (const float*)d_in[11];
    const float* bm1    = (const float*)d_in[12];
    const float* Wm2    = (const float*)d_in[13];
    const float* bm2    = (const float*)d_in[14];
    const float* Wn1    = (const float*)d_in[15];
    const float* bn1    = (const float*)d_in[16];
    const float* Wn2    = (const float*)d_in[17];
    const float* bn2    = (const float*)d_in[18];
    const float* Wc1    = (const float*)d_in[19];
    const float* bc1    = (const float*)d_in[20];
    const float* Wc2    = (const float*)d_in[21];
    const float* Wo1    = (const float*)d_in[22];
    const float* bo1    = (const float*)d_in[23];
    const float* Wo2    = (const float*)d_in[24];
    const float* bo2    = (const float*)d_in[25];
    float* out = (float*)d_out;

    __half *p_wm1, *p_wm2, *p_wc1, *p_wn1, *p_wn2, *p_wo1;
    int *p_deg;
    cudaGetSymbolAddress((void**)&p_wm1, g_wm1);
    cudaGetSymbolAddress((void**)&p_wm2, g_wm2);
    cudaGetSymbolAddress((void**)&p_wc1, g_wc1);
    cudaGetSymbolAddress((void**)&p_wn1, g_wn1);
    cudaGetSymbolAddress((void**)&p_wn2, g_wn2);
    cudaGetSymbolAddress((void**)&p_wo1, g_wo1);
    cudaGetSymbolAddress((void**)&p_deg, g_deg);

    cudaFuncSetAttribute(edge_fused_k, cudaFuncAttributeMaxDynamicSharedMemorySize, FUSE_SMEM);
    cudaFuncSetAttribute(node_fused_k, cudaFuncAttributeMaxDynamicSharedMemorySize, FUSE_SMEM);
    cudaFuncSetAttribute(out_fused_k, cudaFuncAttributeMaxDynamicSharedMemorySize, FUSE_SMEM);

    const int gridE = BB * EE / 128;  // 2500
    const int gridN = BB * NN / 128;  // 1250

    setupA_k<<<194, 256>>>(t, W_t1, b_t1, W_t2, b_t2, emb, W_node, b_node,
                           Wm1, Wm2, Wc1, Wn1, Wn2, Wo1);
    setupB_k<<<4096, 256>>>(types, x, bonds);
    zero_i_k<<<cdiv(NN, 256), 256>>>(p_deg, NN);

    for (int l = 0; l < LL; l++) {
        if (l > 0) prep_k<<<2048, 256>>>(bonds);

        edge_fused_k<<<gridE, 256, FUSE_SMEM>>>(
            p_wm1 + (long)l * 257 * 128, bm1 + l * 128,
            Wm1 + ((long)l * 257 + 256) * 128,
            p_wm2 + (long)l * 16384, bm2 + l * 128,
            p_wc1 + (long)l * 16384, bc1 + l * 128, Wc2 + l * 128, bonds);

        if (l == 0) {
            deg_count_k<<<cdiv(EE, 256), 256>>>(bonds);
            scan_k<<<1, 256>>>();
            fill_k<<<cdiv(EE, 256), 256>>>(bonds);
        }

        agg_gather_k<<<cdiv((long)BB * NN * 32, 256), 256>>>();

        node_fused_k<<<gridN, 256, FUSE_SMEM>>>(
            p_wn1 + (long)l * 256 * 128, bn1 + l * 128,
            p_wn2 + (long)l * 16384, bn2 + l * 128);

        x_update_k<<<cdiv((long)BB * NN * 3, 256), 256>>>();
    }

    out_fused_k<<<gridN, 256, FUSE_SMEM>>>(p_wo1, bo1, Wo2, bo2, x, out);
}

// round 11
// speedup vs baseline: 3.0813x; 1.8118x over previous
#include <cuda_runtime.h>
#include <cuda_fp16.h>
#include <math.h>
#include <stdint.h>

#define BB 8
#define NN 20000
#define EE 40000
#define HH 128
#define TT 64
#define LL 4

__device__ __forceinline__ float silu_f(float v) { return v / (1.f + __expf(-v)); }
__device__ __forceinline__ uint32_t s2u(const void* p) {
    uint32_t a;
    asm("{ .reg .u64 t; cvta.to.shared.u64 t, %1; cvt.u32.u64 %0, t; }" : "=r"(a) : "l"(p));
    return a;
}
__device__ __forceinline__ void cp16(uint32_t dst, const void* src) {
    asm volatile("cp.async.cg.shared.global [%0], [%1], 16;\n" :: "r"(dst), "l"(src));
}
#define CP_COMMIT() asm volatile("cp.async.commit_group;\n" ::: "memory")
template <int N> __device__ __forceinline__ void cp_wait() {
    asm volatile("cp.async.wait_group %0;\n" :: "n"(N) : "memory");
}

// ---------------- scratch (static device globals) --------------------------
__device__ float  g_temb[BB * HH];
__device__ float  g_table4[4 * HH];
__device__ float  g_h[BB * NN * HH];
__device__ __half g_htf[BB * NN * HH];
__device__ __half g_agg[BB * NN * HH];
__device__ float  g_x[BB * NN * 3];
__device__ float  g_cupd[BB * NN * 3];
__device__ float  g_dist[BB * EE];
__device__ float  g_cdn[BB * EE * 3];
__device__ __half g_m[BB * EE * HH];
__device__ int    g_deg[NN];
__device__ int    g_off[NN + 1];
__device__ int    g_cur[NN];
__device__ int    g_csr[2 * EE];
__device__ __half g_wm1[4 * 257 * 128];
__device__ __half g_wm2[4 * 128 * 128];
__device__ __half g_wc1[4 * 128 * 128];
__device__ __half g_wn1[4 * 256 * 128];
__device__ __half g_wn2[4 * 128 * 128];
__device__ __half g_wo1[128 * 128];

// ---------------- mma.sync m16n8k16 core (M=128 tile, 4x2 warp grid) -------
#define LDTh 136
#define LDAh 40
#define LDBh 136

__device__ __forceinline__ void mma16(float* c, const uint32_t* a, const uint32_t* b)
{
    asm volatile(
        "mma.sync.aligned.m16n8k16.row.col.f32.f16.f16.f32 "
        "{%0,%1,%2,%3}, {%4,%5,%6,%7}, {%8,%9}, {%0,%1,%2,%3};"
        : "+f"(c[0]), "+f"(c[1]), "+f"(c[2]), "+f"(c[3])
        : "r"(a[0]), "r"(a[1]), "r"(a[2]), "r"(a[3]), "r"(b[0]), "r"(b[1]));
}

// one 32-K chunk: A (smem, lda halves) x Bs[32][LDBh] -> c[2][8][4]
__device__ __forceinline__ void mma_chunk32(float (&c)[2][8][4],
        const __half* A, int lda, const __half* Bs, int wm, int wn, int lane)
{
#pragma unroll
    for (int s = 0; s < 2; s++) {
        uint32_t a0[4], a1[4];
        {
            int row = (lane & 7) + ((lane >> 3) & 1) * 8;
            int k   = (lane >> 4) * 8 + s * 16;
            uint32_t ad0 = s2u(A + (wm * 32 + row) * lda + k);
            uint32_t ad1 = s2u(A + (wm * 32 + 16 + row) * lda + k);
            asm volatile("ldmatrix.sync.aligned.m8n8.x4.shared.b16 {%0,%1,%2,%3}, [%4];"
                : "=r"(a0[0]), "=r"(a0[1]), "=r"(a0[2]), "=r"(a0[3]) : "r"(ad0));
            asm volatile("ldmatrix.sync.aligned.m8n8.x4.shared.b16 {%0,%1,%2,%3}, [%4];"
                : "=r"(a1[0]), "=r"(a1[1]), "=r"(a1[2]), "=r"(a1[3]) : "r"(ad1));
        }
#pragma unroll
        for (int jj = 0; jj < 4; jj++) {
            uint32_t bf[4];
            int k = (lane & 15) + s * 16;
            int n = wn * 64 + jj * 16 + (lane >> 4) * 8;
            uint32_t bd = s2u(Bs + k * LDBh + n);
            asm volatile("ldmatrix.sync.aligned.m8n8.x4.trans.shared.b16 {%0,%1,%2,%3}, [%4];"
                : "=r"(bf[0]), "=r"(bf[1]), "=r"(bf[2]), "=r"(bf[3]) : "r"(bd));
            mma16(c[0][2 * jj],     a0, bf);
            mma16(c[0][2 * jj + 1], a0, bf + 2);
            mma16(c[1][2 * jj],     a1, bf);
            mma16(c[1][2 * jj + 1], a1, bf + 2);
        }
    }
}

__device__ __forceinline__ void zero_c(float (&c)[2][8][4])
{
#pragma unroll
    for (int i = 0; i < 2; i++)
#pragma unroll
        for (int j = 0; j < 8; j++)
#pragma unroll
            for (int q = 0; q < 4; q++) c[i][j][q] = 0.f;
}

// B chunk (32 x 128 halves) via cp.async
__device__ __forceinline__ void issue_Bh(const __half* __restrict__ W, int k0,
                                         __half* Bsb, int tid)
{
    int row = tid >> 3;
    int off = (tid & 7) * 16;
    const __half* src = W + (long)(k0 + row) * 128 + off;
    uint32_t dst = s2u(Bsb + row * LDBh + off);
    cp16(dst, src);
    cp16(dst + 16, src + 8);
}

// dyn smem: Th[128*LDTh halves] | Bs0[32*LDBh] | Bs1[32*LDBh]
#define OFF_BS0  34816
#define OFF_BS1  43520
#define FUSE_SMEM 52224

// ---------------- fused edge kernel ----------------------------------------
__global__ void __launch_bounds__(256, 2)
edge_fused_k(const __half* __restrict__ Wm1h, const float* __restrict__ bm1,
             const float* __restrict__ w256,
             const __half* __restrict__ Wm2h, const float* __restrict__ bm2,
             const __half* __restrict__ Wc1h, const float* __restrict__ bc1,
             const float* __restrict__ Wc2, const int* __restrict__ bonds)
{
    extern __shared__ char dyn[];
    __half* Th  = (__half*)dyn;
    __half* Bs0 = (__half*)(dyn + OFF_BS0);
    __half* Bs1 = (__half*)(dyn + OFF_BS1);
    __half* Ab0 = Th;
    __half* Ab1 = Th + 128 * LDAh;

    __shared__ float b1s[128], b2s[128], bc1s[128], wc2s[128], wds[128], dists[128];
    __shared__ float cwacc[128];
    __shared__ const __half* pA0[128];
    __shared__ const __half* pA1[128];

    const int tid = threadIdx.x;
    const int wid = tid >> 5, lane = tid & 31;
    const int wm = wid & 3, wn = wid >> 2;
    const int lr = lane >> 2, lc2 = (lane & 3) * 2;
    const long row0 = (long)blockIdx.x * 128;

    if (tid < 128) {
        b1s[tid] = bm1[tid]; b2s[tid] = bm2[tid];
        bc1s[tid] = bc1[tid]; wc2s[tid] = Wc2[tid]; wds[tid] = w256[tid];
        dists[tid] = g_dist[row0 + tid];
        cwacc[tid] = 0.f;
        long gr = row0 + tid;
        int b = (int)(gr / EE), e = (int)(gr - (long)b * EE);
        int s = bonds[2 * e], d = bonds[2 * e + 1];
        pA0[tid] = g_htf + ((long)b * NN + s) * HH;
        pA1[tid] = g_htf + ((long)b * NN + d) * HH;
    }
    __syncthreads();

    const int arow = tid >> 1;
    const int aoff = (tid & 1) * 16;

    auto issue_A = [&](int ch, __half* Asb) {
        int k0 = ch << 5;
        const __half* src = ((k0 < 128) ? pA0[arow] : pA1[arow]) + (k0 & 127) + aoff;
        uint32_t dst = s2u(Asb + arow * LDAh + aoff);
        cp16(dst, src);
        cp16(dst + 16, src + 8);
    };

    float c[2][8][4];

    // ---- stage 1: m1 = silu(gather @ Wm1 + dist*w256 + b), K=256 ----
    zero_c(c);
    issue_A(0, Ab0); issue_Bh(Wm1h, 0, Bs0, tid); CP_COMMIT();
    issue_A(1, Ab1); issue_Bh(Wm1h, 32, Bs1, tid); CP_COMMIT();
    for (int ch = 0; ch < 8; ch++) {
        if (ch == 7) cp_wait<0>(); else cp_wait<1>();
        __syncthreads();
        mma_chunk32(c, (ch & 1) ? Ab1 : Ab0, LDAh, (ch & 1) ? Bs1 : Bs0, wm, wn, lane);
        __syncthreads();
        if (ch + 2 < 8) {
            issue_A(ch + 2, (ch & 1) ? Ab1 : Ab0);
            issue_Bh(Wm1h, (ch + 2) * 32, (ch & 1) ? Bs1 : Bs0, tid);
            CP_COMMIT();
        }
    }
#pragma unroll
    for (int i = 0; i < 2; i++) {
        int r0 = wm * 32 + i * 16 + lr;
        float dv0 = dists[r0], dv1 = dists[r0 + 8];
#pragma unroll
        for (int j = 0; j < 8; j++) {
            int col = wn * 64 + j * 8 + lc2;
            float* cc = c[i][j];
            float v0 = silu_f(cc[0] + b1s[col]     + dv0 * wds[col]);
            float v1 = silu_f(cc[1] + b1s[col + 1] + dv0 * wds[col + 1]);
            float v2 = silu_f(cc[2] + b1s[col]     + dv1 * wds[col]);
            float v3 = silu_f(cc[3] + b1s[col + 1] + dv1 * wds[col + 1]);
            *(__half2*)&Th[r0 * LDTh + col]       = __floats2half2_rn(v0, v1);
            *(__half2*)&Th[(r0 + 8) * LDTh + col] = __floats2half2_rn(v2, v3);
        }
    }
    __syncthreads();

    // ---- stage 2: m = silu(m1 @ Wm2 + b) -> g_m (half) and Th ----
    zero_c(c);
    issue_Bh(Wm2h, 0, Bs0, tid); CP_COMMIT();
    issue_Bh(Wm2h, 32, Bs1, tid); CP_COMMIT();
    for (int ch = 0; ch < 4; ch++) {
        if (ch == 3) cp_wait<0>(); else cp_wait<1>();
        __syncthreads();
        mma_chunk32(c, Th + ch * 32, LDTh, (ch & 1) ? Bs1 : Bs0, wm, wn, lane);
        __syncthreads();
        if (ch + 2 < 4) { issue_Bh(Wm2h, (ch + 2) * 32, (ch & 1) ? Bs1 : Bs0, tid); CP_COMMIT(); }
    }
#pragma unroll
    for (int i = 0; i < 2; i++) {
        int r0 = wm * 32 + i * 16 + lr;
#pragma unroll
        for (int j = 0; j < 8; j++) {
            int col = wn * 64 + j * 8 + lc2;
            float* cc = c[i][j];
            __half2 h0 = __floats2half2_rn(silu_f(cc[0] + b2s[col]),
                                           silu_f(cc[1] + b2s[col + 1]));
            __half2 h1 = __floats2half2_rn(silu_f(cc[2] + b2s[col]),
                                           silu_f(cc[3] + b2s[col + 1]));
            *(__half2*)&Th[r0 * LDTh + col]       = h0;
            *(__half2*)&Th[(r0 + 8) * LDTh + col] = h1;
            *(__half2*)&g_m[(row0 + r0) * HH + col]     = h0;
            *(__half2*)&g_m[(row0 + r0 + 8) * HH + col] = h1;
        }
    }
    __syncthreads();

    // ---- stage 3: cw = silu(m @ Wc1 + b) . Wc2; coord atomics ----
    zero_c(c);
    issue_Bh(Wc1h, 0, Bs0, tid); CP_COMMIT();
    issue_Bh(Wc1h, 32, Bs1, tid); CP_COMMIT();
    for (int ch = 0; ch < 4; ch++) {
        if (ch == 3) cp_wait<0>(); else cp_wait<1>();
        __syncthreads();
        mma_chunk32(c, Th + ch * 32, LDTh, (ch & 1) ? Bs1 : Bs0, wm, wn, lane);
        __syncthreads();
        if (ch + 2 < 4) { issue_Bh(Wc1h, (ch + 2) * 32, (ch & 1) ? Bs1 : Bs0, tid); CP_COMMIT(); }
    }
#pragma unroll
    for (int i = 0; i < 2; i++) {
        float s0 = 0.f, s1 = 0.f;
#pragma unroll
        for (int j = 0; j < 8; j++) {
            int col = wn * 64 + j * 8 + lc2;
            float* cc = c[i][j];
            s0 += silu_f(cc[0] + bc1s[col]) * wc2s[col]
                + silu_f(cc[1] + bc1s[col + 1]) * wc2s[col + 1];
            s1 += silu_f(cc[2] + bc1s[col]) * wc2s[col]
                + silu_f(cc[3] + bc1s[col + 1]) * wc2s[col + 1];
        }
        s0 += __shfl_xor_sync(0xffffffffu, s0, 1);
        s0 += __shfl_xor_sync(0xffffffffu, s0, 2);
        s1 += __shfl_xor_sync(0xffffffffu, s1, 1);
        s1 += __shfl_xor_sync(0xffffffffu, s1, 2);
        if ((lane & 3) == 0) {
            int r0 = wm * 32 + i * 16 + lr;
            atomicAdd(&cwacc[r0], s0);
            atomicAdd(&cwacc[r0 + 8], s1);
        }
    }
    __syncthreads();
    if (tid < 128) {
        float cw = cwacc[tid];
        long gr = row0 + tid;
        int b = (int)(gr / EE), e = (int)(gr - (long)b * EE);
        int s = bonds[2 * e], d = bonds[2 * e + 1];
        const float* cd = g_cdn + gr * 3;
#pragma unroll
        for (int cc = 0; cc < 3; cc++) {
            float u = cd[cc] * cw;
            atomicAdd(&g_cupd[((long)b * NN + d) * 3 + cc], u);
            atomicAdd(&g_cupd[((long)b * NN + s) * 3 + cc], -u);
        }
    }
}

// ---------------- fused node kernel ----------------------------------------
__global__ void __launch_bounds__(256, 2)
node_fused_k(const __half* __restrict__ Wn1h, const float* __restrict__ bn1,
             const __half* __restrict__ Wn2h, const float* __restrict__ bn2)
{
    extern __shared__ char dyn[];
    __half* Th  = (__half*)dyn;
    __half* Bs0 = (__half*)(dyn + OFF_BS0);
    __half* Bs1 = (__half*)(dyn + OFF_BS1);
    __half* Ab0 = Th;
    __half* Ab1 = Th + 128 * LDAh;

    __shared__ float b1s[128], b2s[128];

    const int tid = threadIdx.x;
    const int wid = tid >> 5, lane = tid & 31;
    const int wm = wid & 3, wn = wid >> 2;
    const int lr = lane >> 2, lc2 = (lane & 3) * 2;
    const long row0 = (long)blockIdx.x * 128;

    if (tid < 128) { b1s[tid] = bn1[tid]; b2s[tid] = bn2[tid]; }
    __syncthreads();

    const int arow = tid >> 1;
    const int aoff = (tid & 1) * 16;
    const long gra = row0 + arow;

    auto issue_A = [&](int ch, __half* Asb) {
        int k0 = ch << 5;
        const __half* src = ((k0 < 128) ? (g_htf + gra * HH) : (g_agg + gra * HH))
                            + (k0 & 127) + aoff;
        uint32_t dst = s2u(Asb + arow * LDAh + aoff);
        cp16(dst, src);
        cp16(dst + 16, src + 8);
    };

    float c[2][8][4];

    // ---- stage 1: n1 = silu([h|agg] @ Wn1 + b), K=256 ----
    zero_c(c);
    issue_A(0, Ab0); issue_Bh(Wn1h, 0, Bs0, tid); CP_COMMIT();
    issue_A(1, Ab1); issue_Bh(Wn1h, 32, Bs1, tid); CP_COMMIT();
    for (int ch = 0; ch < 8; ch++) {
        if (ch == 7) cp_wait<0>(); else cp_wait<1>();
        __syncthreads();
        mma_chunk32(c, (ch & 1) ? Ab1 : Ab0, LDAh, (ch & 1) ? Bs1 : Bs0, wm, wn, lane);
        __syncthreads();
        if (ch + 2 < 8) {
            issue_A(ch + 2, (ch & 1) ? Ab1 : Ab0);
            issue_Bh(Wn1h, (ch + 2) * 32, (ch & 1) ? Bs1 : Bs0, tid);
            CP_COMMIT();
        }
    }
#pragma unroll
    for (int i = 0; i < 2; i++) {
        int r0 = wm * 32 + i * 16 + lr;
#pragma unroll
        for (int j = 0; j < 8; j++) {
            int col = wn * 64 + j * 8 + lc2;
            float* cc = c[i][j];
            *(__half2*)&Th[r0 * LDTh + col] =
                __floats2half2_rn(silu_f(cc[0] + b1s[col]), silu_f(cc[1] + b1s[col + 1]));
            *(__half2*)&Th[(r0 + 8) * LDTh + col] =
                __floats2half2_rn(silu_f(cc[2] + b1s[col]), silu_f(cc[3] + b1s[col + 1]));
        }
    }
    __syncthreads();

    // ---- stage 2: h += n1 @ Wn2 + b (refresh g_htf) ----
    zero_c(c);
    issue_Bh(Wn2h, 0, Bs0, tid); CP_COMMIT();
    issue_Bh(Wn2h, 32, Bs1, tid); CP_COMMIT();
    for (int ch = 0; ch < 4; ch++) {
        if (ch == 3) cp_wait<0>(); else cp_wait<1>();
        __syncthreads();
        mma_chunk32(c, Th + ch * 32, LDTh, (ch & 1) ? Bs1 : Bs0, wm, wn, lane);
        __syncthreads();
        if (ch + 2 < 4) { issue_Bh(Wn2h, (ch + 2) * 32, (ch & 1) ? Bs1 : Bs0, tid); CP_COMMIT(); }
    }
#pragma unroll
    for (int i = 0; i < 2; i++) {
        int r0 = wm * 32 + i * 16 + lr;
#pragma unroll
        for (int j = 0; j < 8; j++) {
            int col = wn * 64 + j * 8 + lc2;
            float* cc = c[i][j];
            long base0 = (row0 + r0) * HH + col;
            long base1 = (row0 + r0 + 8) * HH + col;
            float2 h0 = *(float2*)&g_h[base0];
            float2 h1 = *(float2*)&g_h[base1];
            float o0 = h0.x + cc[0] + b2s[col];
            float o1 = h0.y + cc[1] + b2s[col + 1];
            float o2 = h1.x + cc[2] + b2s[col];
            float o3 = h1.y + cc[3] + b2s[col + 1];
            *(float2*)&g_h[base0] = make_float2(o0, o1);
            *(float2*)&g_h[base1] = make_float2(o2, o3);
            *(__half2*)&g_htf[base0] = __floats2half2_rn(o0, o1);
            *(__half2*)&g_htf[base1] = __floats2half2_rn(o2, o3);
        }
    }
}

// ---------------- fused output kernel --------------------------------------
__global__ void __launch_bounds__(256, 2)
out_fused_k(const __half* __restrict__ Wo1h, const float* __restrict__ bo1,
            const float* __restrict__ Wo2, const float* __restrict__ bo2,
            const float* __restrict__ x_in, float* __restrict__ out)
{
    extern __shared__ char dyn[];
    __half* Th  = (__half*)dyn;
    __half* Bs0 = (__half*)(dyn + OFF_BS0);
    __half* Bs1 = (__half*)(dyn + OFF_BS1);
    __half* Ab0 = Th;
    __half* Ab1 = Th + 128 * LDAh;

    __shared__ float b1s[128];
    __shared__ float wo2s[128 * 3];
    __shared__ float oacc[128 * 3];

    const int tid = threadIdx.x;
    const int wid = tid >> 5, lane = tid & 31;
    const int wm = wid & 3, wn = wid >> 2;
    const int lr = lane >> 2, lc2 = (lane & 3) * 2;
    const long row0 = (long)blockIdx.x * 128;

    if (tid < 128) b1s[tid] = bo1[tid];
    for (int i = tid; i < 384; i += 256) { wo2s[i] = Wo2[i]; oacc[i] = 0.f; }
    __syncthreads();

    const int arow = tid >> 1;
    const int aoff = (tid & 1) * 16;
    const long gra = row0 + arow;

    auto issue_A = [&](int ch, __half* Asb) {
        const __half* src = g_htf + gra * HH + (ch << 5) + aoff;
        uint32_t dst = s2u(Asb + arow * LDAh + aoff);
        cp16(dst, src);
        cp16(dst + 16, src + 8);
    };

    float c[2][8][4];
    zero_c(c);
    issue_A(0, Ab0); issue_Bh(Wo1h, 0, Bs0, tid); CP_COMMIT();
    issue_A(1, Ab1); issue_Bh(Wo1h, 32, Bs1, tid); CP_COMMIT();
    for (int ch = 0; ch < 4; ch++) {
        if (ch == 3) cp_wait<0>(); else cp_wait<1>();
        __syncthreads();
        mma_chunk32(c, (ch & 1) ? Ab1 : Ab0, LDAh, (ch & 1) ? Bs1 : Bs0, wm, wn, lane);
        __syncthreads();
        if (ch + 2 < 4) {
            issue_A(ch + 2, (ch & 1) ? Ab1 : Ab0);
            issue_Bh(Wo1h, (ch + 2) * 32, (ch & 1) ? Bs1 : Bs0, tid);
            CP_COMMIT();
        }
    }
#pragma unroll
    for (int i = 0; i < 2; i++) {
        float s0[3] = {0.f, 0.f, 0.f};
        float s1[3] = {0.f, 0.f, 0.f};
#pragma unroll
        for (int j = 0; j < 8; j++) {
            int col = wn * 64 + j * 8 + lc2;
            float* cc = c[i][j];
            float v0 = silu_f(cc[0] + b1s[col]);
            float v1 = silu_f(cc[1] + b1s[col + 1]);
            float v2 = silu_f(cc[2] + b1s[col]);
            float v3 = silu_f(cc[3] + b1s[col + 1]);
#pragma unroll
            for (int k = 0; k < 3; k++) {
                s0[k] += v0 * wo2s[col * 3 + k] + v1 * wo2s[(col + 1) * 3 + k];
                s1[k] += v2 * wo2s[col * 3 + k] + v3 * wo2s[(col + 1) * 3 + k];
            }
        }
#pragma unroll
        for (int k = 0; k < 3; k++) {
            s0[k] += __shfl_xor_sync(0xffffffffu, s0[k], 1);
            s0[k] += __shfl_xor_sync(0xffffffffu, s0[k], 2);
            s1[k] += __shfl_xor_sync(0xffffffffu, s1[k], 1);
            s1[k] += __shfl_xor_sync(0xffffffffu, s1[k], 2);
        }
        if ((lane & 3) == 0) {
            int r0 = wm * 32 + i * 16 + lr;
#pragma unroll
            for (int k = 0; k < 3; k++) {
                atomicAdd(&oacc[r0 * 3 + k], s0[k]);
                atomicAdd(&oacc[(r0 + 8) * 3 + k], s1[k]);
            }
        }
    }
    __syncthreads();
    if (tid < 128) {
        long base = (row0 + tid) * 3;
#pragma unroll
        for (int cc = 0; cc < 3; cc++)
            out[base + cc] = oacc[tid * 3 + cc] + bo2[cc] + g_x[base + cc] - x_in[base + cc];
    }
}

// ---------------- setup kernels --------------------------------------------
__global__ void setupA_k(const float* __restrict__ t,
                         const float* __restrict__ W1, const float* __restrict__ b1,
                         const float* __restrict__ W2, const float* __restrict__ b2,
                         const float* __restrict__ emb,
                         const float* __restrict__ Wn, const float* __restrict__ bn,
                         const float* __restrict__ Wm1, const float* __restrict__ Wm2,
                         const float* __restrict__ Wc1, const float* __restrict__ Wn1,
                         const float* __restrict__ Wn2, const float* __restrict__ Wo1)
{
    const int tid = threadIdx.x;
    if (blockIdx.x == 0) {
        __shared__ float te[BB][TT];
        __shared__ float s1[BB][HH];
        const int half = TT / 2;
        for (int idx = tid; idx < BB * TT; idx += 256) {
            int b = idx / TT, k = idx % TT;
            int kk = (k < half) ? k : (k - half);
            float f = __expf((float)kk * (-logf(10000.f) / (float)(half - 1)));
            float a = t[b] * f;
            te[b][k] = (k < half) ? sinf(a) : cosf(a);
        }
        __syncthreads();
        if (tid < 128) {
            for (int b = 0; b < BB; b++) {
                float acc = b1[tid];
                for (int k = 0; k < TT; k++) acc += te[b][k] * W1[k * HH + tid];
                s1[b][tid] = silu_f(acc);
            }
        }
        __syncthreads();
        if (tid < 128) {
            for (int b = 0; b < BB; b++) {
                float acc = b2[tid];
                for (int k = 0; k < HH; k++) acc += s1[b][k] * W2[k * HH + tid];
                g_temb[b * HH + tid] = acc;
            }
        }
    } else if (blockIdx.x == 1) {
        for (int idx = tid; idx < 4 * HH; idx += 256) {
            int a = idx >> 7, j = idx & 127;
            float acc = bn[j];
            for (int k = 0; k < HH; k++) acc += emb[a * HH + k] * Wn[k * HH + j];
            g_table4[idx] = acc;
        }
    } else {
        long rid = (long)(blockIdx.x - 2) * 256 + tid;
        long rstride = (long)(gridDim.x - 2) * 256;
        for (long i = rid; i < 4L * 257 * 128; i += rstride) g_wm1[i] = __float2half_rn(Wm1[i]);
        for (long i = rid; i < 4L * 128 * 128; i += rstride) g_wm2[i] = __float2half_rn(Wm2[i]);
        for (long i = rid; i < 4L * 128 * 128; i += rstride) g_wc1[i] = __float2half_rn(Wc1[i]);
        for (long i = rid; i < 4L * 256 * 128; i += rstride) g_wn1[i] = __float2half_rn(Wn1[i]);
        for (long i = rid; i < 4L * 128 * 128; i += rstride) g_wn2[i] = __float2half_rn(Wn2[i]);
        for (long i = rid; i < 128L * 128; i += rstride)     g_wo1[i] = __float2half_rn(Wo1[i]);
    }
}

__global__ void setupB_k(const int* __restrict__ types, const float* __restrict__ x,
                         const int* __restrict__ bonds)
{
    const long N1 = (long)BB * NN * HH;
    const long N2 = N1 + BB * NN * 3;
    const long N3 = N2 + BB * NN * 3;
    const long N4 = N3 + BB * EE;
    const long stride = (long)gridDim.x * 256;
    for (long idx = (long)blockIdx.x * 256 + threadIdx.x; idx < N4; idx += stride) {
        if (idx < N1) {
            int j = (int)(idx & 127);
            long bn = idx >> 7;
            int n = (int)(bn % NN), b = (int)(bn / NN);
            float v = g_table4[types[n] * HH + j] + g_temb[b * HH + j];
            g_h[idx] = v;
            g_htf[idx] = __float2half_rn(v);
        } else if (idx < N2) {
            long i = idx - N1;
            g_x[i] = x[i];
        } else if (idx < N3) {
            g_cupd[idx - N2] = 0.f;
        } else {
            long i = idx - N3;
            int b = (int)(i / EE), e = (int)(i - (long)b * EE);
            int s = bonds[2 * e], d = bonds[2 * e + 1];
            const float* xs = x + ((long)b * NN + s) * 3;
            const float* xd = x + ((long)b * NN + d) * 3;
            float dx = xd[0] - xs[0], dy = xd[1] - xs[1], dz = xd[2] - xs[2];
            float dist = sqrtf(dx * dx + dy * dy + dz * dz);
            g_dist[i] = dist;
            float inv = 1.f / (dist + 1e-8f);
            g_cdn[i * 3 + 0] = dx * inv;
            g_cdn[i * 3 + 1] = dy * inv;
            g_cdn[i * 3 + 2] = dz * inv;
        }
    }
}

__global__ void prep_k(const int* __restrict__ bonds)
{
    const long N1 = (long)BB * NN * 3;
    const long N2 = N1 + BB * EE;
    const long stride = (long)gridDim.x * 256;
    for (long idx = (long)blockIdx.x * 256 + threadIdx.x; idx < N2; idx += stride) {
        if (idx < N1) {
            g_cupd[idx] = 0.f;
        } else {
            long i = idx - N1;
            int b = (int)(i / EE), e = (int)(i - (long)b * EE);
            int s = bonds[2 * e], d = bonds[2 * e + 1];
            const float* xs = g_x + ((long)b * NN + s) * 3;
            const float* xd = g_x + ((long)b * NN + d) * 3;
            float dx = xd[0] - xs[0], dy = xd[1] - xs[1], dz = xd[2] - xs[2];
            float dist = sqrtf(dx * dx + dy * dy + dz * dz);
            g_dist[i] = dist;
            float inv = 1.f / (dist + 1e-8f);
            g_cdn[i * 3 + 0] = dx * inv;
            g_cdn[i * 3 + 1] = dy * inv;
            g_cdn[i * 3 + 2] = dz * inv;
        }
    }
}

// ---------------- CSR + gather kernels --------------------------------------
__global__ void zero_i_k(int* __restrict__ p, int n)
{
    int idx = blockIdx.x * 256 + threadIdx.x;
    if (idx < n) p[idx] = 0;
}
__global__ void deg_count_k(const int* __restrict__ bonds)
{
    int e = blockIdx.x * 256 + threadIdx.x;
    if (e >= EE) return;
    atomicAdd(&g_deg[bonds[2 * e]], 1);
    atomicAdd(&g_deg[bonds[2 * e + 1]], 1);
}
__global__ void scan_k()
{
    __shared__ int sh[256];
    __shared__ int base;
    int tid = threadIdx.x;
    if (tid == 0) base = 0;
    __syncthreads();
    for (int i0 = 0; i0 < NN; i0 += 256) {
        int i = i0 + tid;
        int v = (i < NN) ? g_deg[i] : 0;
        sh[tid] = v;
        __syncthreads();
        for (int o = 1; o < 256; o <<= 1) {
            int t = (tid >= o) ? sh[tid - o] : 0;
            __syncthreads();
            sh[tid] += t;
            __syncthreads();
        }
        int excl = base + sh[tid] - v;
        if (i < NN) { g_off[i] = excl; g_cur[i] = excl; }
        __syncthreads();
        if (tid == 255) base += sh[255];
        __syncthreads();
    }
    if (tid == 0) g_off[NN] = base;
}
__global__ void fill_k(const int* __restrict__ bonds)
{
    int e = blockIdx.x * 256 + threadIdx.x;
    if (e >= EE) return;
    int s = bonds[2 * e], d = bonds[2 * e + 1];
    int p = atomicAdd(&g_cur[s], 1); g_csr[p] = e;
    int q = atomicAdd(&g_cur[d], 1); g_csr[q] = e;
}

__global__ void agg_gather_k()
{
    int warp = (blockIdx.x * 256 + threadIdx.x) >> 5;
    int lane = threadIdx.x & 31;
    if (warp >= BB * NN) return;
    int b = warp / NN, n = warp - b * NN;
    int o0 = g_off[n], o1 = g_off[n + 1];
    float acc[4] = {0.f, 0.f, 0.f, 0.f};
    for (int j = o0; j < o1; j++) {
        int e = g_csr[j];
        const __half2* row = (const __half2*)(g_m + ((long)b * EE + e) * HH) + lane * 2;
        float2 v0 = __half22float2(row[0]);
        float2 v1 = __half22float2(row[1]);
        acc[0] += v0.x; acc[1] += v0.y; acc[2] += v1.x; acc[3] += v1.y;
    }
    __half2* dst = (__half2*)(g_agg + (long)warp * HH) + lane * 2;
    dst[0] = __floats2half2_rn(acc[0], acc[1]);
    dst[1] = __floats2half2_rn(acc[2], acc[3]);
}

__global__ void x_update_k()
{
    int idx = blockIdx.x * 256 + threadIdx.x;
    if (idx >= BB * NN * 3) return;
    int n = (idx / 3) % NN;
    g_x[idx] += g_cupd[idx] / fmaxf((float)g_deg[n], 1.f);
}

// ---------------- launch ---------------------------------------------------
static inline int cdiv(long n, int b) { return (int)((n + b - 1) / b); }

extern "C" void kernel_launch(void* const* d_in, const int* in_sizes, int n_in,
                              void* d_out, int out_size)
{
    const float* x      = (const float*)d_in[0];
    const float* t      = (const float*)d_in[1];
    const int*   types  = (const int*)d_in[2];
    const int*   bonds  = (const int*)d_in[3];
    const float* emb    = (const float*)d_in[4];
    const float* W_t1   = (const float*)d_in[5];
    const float* b_t1   = (const float*)d_in[6];
    const float* W_t2   = (const float*)d_in[7];
    const float* b_t2   = (const float*)d_in[8];
    const float* W_node = (const float*)d_in[9];
    const float* b_node = (const float*)d_in[10];
    const float* Wm1    = (const float*)d_in[11];
    const float* bm1    = (const float*)d_in[12];
    const float* Wm2    = (const float*)d_in[13];
    const float* bm2    = (const float*)d_in[14];
    const float* Wn1    = (const float*)d_in[15];
    const float* bn1    = (const float*)d_in[16];
    const float* Wn2    = (const float*)d_in[17];
    const float* bn2    = (const float*)d_in[18];
    const float* Wc1    = (const float*)d_in[19];
    const float* bc1    = (const float*)d_in[20];
    const float* Wc2    = (const float*)d_in[21];
    const float* Wo1    = (const float*)d_in[22];
    const float* bo1    = (const float*)d_in[23];
    const float* Wo2    = (const float*)d_in[24];
    const float* bo2    = (const float*)d_in[25];
    float* out = (float*)d_out;

    __half *p_wm1, *p_wm2, *p_wc1, *p_wn1, *p_wn2, *p_wo1;
    int *p_deg;
    cudaGetSymbolAddress((void**)&p_wm1, g_wm1);
    cudaGetSymbolAddress((void**)&p_wm2, g_wm2);
    cudaGetSymbolAddress((void**)&p_wc1, g_wc1);
    cudaGetSymbolAddress((void**)&p_wn1, g_wn1);
    cudaGetSymbolAddress((void**)&p_wn2, g_wn2);
    cudaGetSymbolAddress((void**)&p_wo1, g_wo1);
    cudaGetSymbolAddress((void**)&p_deg, g_deg);

    cudaFuncSetAttribute(edge_fused_k, cudaFuncAttributeMaxDynamicSharedMemorySize, FUSE_SMEM);
    cudaFuncSetAttribute(node_fused_k, cudaFuncAttributeMaxDynamicSharedMemorySize, FUSE_SMEM);
    cudaFuncSetAttribute(out_fused_k, cudaFuncAttributeMaxDynamicSharedMemorySize, FUSE_SMEM);

    const int gridE = BB * EE / 128;  // 2500
    const int gridN = BB * NN / 128;  // 1250

    setupA_k<<<194, 256>>>(t, W_t1, b_t1, W_t2, b_t2, emb, W_node, b_node,
                           Wm1, Wm2, Wc1, Wn1, Wn2, Wo1);
    setupB_k<<<4096, 256>>>(types, x, bonds);
    zero_i_k<<<cdiv(NN, 256), 256>>>(p_deg, NN);

    for (int l = 0; l < LL; l++) {
        if (l > 0) prep_k<<<2048, 256>>>(bonds);

        edge_fused_k<<<gridE, 256, FUSE_SMEM>>>(
            p_wm1 + (long)l * 257 * 128, bm1 + l * 128,
            Wm1 + ((long)l * 257 + 256) * 128,
            p_wm2 + (long)l * 16384, bm2 + l * 128,
            p_wc1 + (long)l * 16384, bc1 + l * 128, Wc2 + l * 128, bonds);

        if (l == 0) {
            deg_count_k<<<cdiv(EE, 256), 256>>>(bonds);
            scan_k<<<1, 256>>>();
            fill_k<<<cdiv(EE, 256), 256>>>(bonds);
        }

        agg_gather_k<<<cdiv((long)BB * NN * 32, 256), 256>>>();

        node_fused_k<<<gridN, 256, FUSE_SMEM>>>(
            p_wn1 + (long)l * 256 * 128, bn1 + l * 128,
            p_wn2 + (long)l * 16384, bn2 + l * 128);

        x_update_k<<<cdiv((long)BB * NN * 3, 256), 256>>>();
    }

    out_fused_k<<<gridN, 256, FUSE_SMEM>>>(p_wo1, bo1, Wo2, bo2, x, out);
}